// round 1
// baseline (speedup 1.0000x reference)
#include <cuda_runtime.h>
#include <math.h>

#define D_MODEL   768
#define D_STATE   64
#define D_CONV    4
#define HEADDIM   64
#define D_INNER   1536
#define NHEADS    24
#define CONV_DIM  1664          // D_INNER + 2*D_STATE
#define D_IN_PROJ 3224          // 2*D_INNER + 2*D_STATE + NHEADS
#define BATCH     2
#define SEQLEN    4096
#define ROWS      (BATCH*SEQLEN)   // 8192

// ---------------- scratch (device globals; no allocation) ----------------
__device__ float g_zxbcdt[(size_t)ROWS * D_IN_PROJ];   // ~105.6 MB
__device__ float g_xBC[(size_t)ROWS * CONV_DIM];       // ~54.5 MB (post conv+silu)
__device__ float g_y[(size_t)ROWS * D_INNER];          // ~50.3 MB
__device__ float g_dt[ROWS * NHEADS];
__device__ float g_dA[ROWS * NHEADS];

// ---------------- 128x128x8 fp32 SGEMM, 256 threads, 8x8 microtile ----------------
// C[M,N] = A[M,K] @ B[K,N], row-major. Requires: M % 128 == 0, K % 8 == 0, N % 8 == 0.
__global__ void __launch_bounds__(256) sgemm128(const float* __restrict__ A,
                                                const float* __restrict__ B,
                                                float* __restrict__ C,
                                                int M, int N, int K) {
    __shared__ float As[8][128];
    __shared__ float Bs[8][128];
    const int tid = threadIdx.x;
    const int tx = tid & 15;        // 0..15  -> 8 cols each
    const int ty = tid >> 4;        // 0..15  -> 8 rows each
    const int blockRow = blockIdx.y * 128;
    const int blockCol = blockIdx.x * 128;

    const int aRow = tid >> 1;          // 0..127
    const int aCol = (tid & 1) * 4;     // 0 or 4
    const int bRow = tid >> 5;          // 0..7
    const int bCol = (tid & 31) * 4;    // 0..124

    const float* Aptr = A + (size_t)(blockRow + aRow) * K + aCol;
    const int    colB = blockCol + bCol;

    float acc[8][8];
#pragma unroll
    for (int i = 0; i < 8; i++)
#pragma unroll
        for (int j = 0; j < 8; j++) acc[i][j] = 0.f;

    for (int k0 = 0; k0 < K; k0 += 8) {
        float4 av = *(const float4*)(Aptr + k0);
        As[aCol + 0][aRow] = av.x;
        As[aCol + 1][aRow] = av.y;
        As[aCol + 2][aRow] = av.z;
        As[aCol + 3][aRow] = av.w;

        float4 bv = make_float4(0.f, 0.f, 0.f, 0.f);
        if (colB < N) bv = *(const float4*)(B + (size_t)(k0 + bRow) * N + colB);
        *(float4*)&Bs[bRow][bCol] = bv;

        __syncthreads();
#pragma unroll
        for (int kk = 0; kk < 8; kk++) {
            float a[8], b[8];
            *(float4*)&a[0] = *(const float4*)&As[kk][ty * 8];
            *(float4*)&a[4] = *(const float4*)&As[kk][ty * 8 + 4];
            *(float4*)&b[0] = *(const float4*)&Bs[kk][tx * 8];
            *(float4*)&b[4] = *(const float4*)&Bs[kk][tx * 8 + 4];
#pragma unroll
            for (int i = 0; i < 8; i++)
#pragma unroll
                for (int j = 0; j < 8; j++)
                    acc[i][j] += a[i] * b[j];
        }
        __syncthreads();
    }

    const int colbase = blockCol + tx * 8;   // multiple of 8; N % 8 == 0
    if (colbase < N) {
#pragma unroll
        for (int i = 0; i < 8; i++) {
            float* Cp = C + (size_t)(blockRow + ty * 8 + i) * N + colbase;
            *(float4*)(Cp + 0) = *(float4*)&acc[i][0];
            *(float4*)(Cp + 4) = *(float4*)&acc[i][4];
        }
    }
}

// ---------------- dt = softplus(raw + bias); dA = exp(dt * A) ----------------
__global__ void dt_kernel(const float* __restrict__ dt_bias,
                          const float* __restrict__ A_log) {
    int idx = blockIdx.x * blockDim.x + threadIdx.x;
    if (idx >= ROWS * NHEADS) return;
    int h = idx % NHEADS;
    int row = idx / NHEADS;
    float v = g_zxbcdt[(size_t)row * D_IN_PROJ + (D_INNER + CONV_DIM) + h] + dt_bias[h];
    float dtv = (v > 20.f) ? v : log1pf(expf(v));
    float A = -expf(A_log[h]);
    g_dt[idx] = dtv;
    g_dA[idx] = expf(dtv * A);
}

// ---------------- causal depthwise conv (width 4) + bias + silu ----------------
__global__ void conv_kernel(const float* __restrict__ conv_w,
                            const float* __restrict__ conv_b) {
    int idx = blockIdx.x * blockDim.x + threadIdx.x;
    if (idx >= ROWS * CONV_DIM) return;
    int c = idx % CONV_DIM;
    int row = idx / CONV_DIM;
    int l = row & (SEQLEN - 1);
    float acc = conv_b[c];
#pragma unroll
    for (int k = 0; k < D_CONV; k++) {
        int ls = l + k - (D_CONV - 1);
        if (ls >= 0)
            acc += g_zxbcdt[(size_t)(row + k - (D_CONV - 1)) * D_IN_PROJ + D_INNER + c] *
                   conv_w[c * D_CONV + k];
    }
    g_xBC[idx] = acc / (1.f + expf(-acc));   // silu
}

// ---------------- sequential SSM scan: one block per (b,h) ----------------
// 512 threads: p = tid>>3 (0..63), each handles 8 state indices n0 = (tid&7)*8.
__global__ void __launch_bounds__(512) scan_kernel(const float* __restrict__ Dparam) {
    __shared__ float sbuf[2][200];   // [x:0..63][B:64..127][C:128..191][dt:192][dA:193]
    const int tid = threadIdx.x;
    const int bh = blockIdx.x;
    const int b = bh / NHEADS, h = bh % NHEADS;
    const int p = tid >> 3;
    const int ng = tid & 7;
    const int n0 = ng * 8;

    float hreg[8];
#pragma unroll
    for (int i = 0; i < 8; i++) hreg[i] = 0.f;
    const float Dh = Dparam[h];

    const float* xbase  = g_xBC + (size_t)b * SEQLEN * CONV_DIM;
    const float* dtbase = g_dt + (size_t)b * SEQLEN * NHEADS + h;
    const float* dAbase = g_dA + (size_t)b * SEQLEN * NHEADS + h;
    float*       ybase  = g_y + (size_t)b * SEQLEN * D_INNER + h * HEADDIM;

    for (int t = 0; t < SEQLEN; t++) {
        float* sb = sbuf[t & 1];
        const float* rowp = xbase + (size_t)t * CONV_DIM;
        if (tid < 64)        sb[tid] = rowp[h * HEADDIM + tid];
        else if (tid < 128)  sb[tid] = rowp[D_INNER + (tid - 64)];             // B
        else if (tid < 192)  sb[tid] = rowp[D_INNER + D_STATE + (tid - 128)];  // C
        else if (tid == 192) sb[192] = dtbase[t * NHEADS];
        else if (tid == 193) sb[193] = dAbase[t * NHEADS];
        __syncthreads();

        const float dt_t = sb[192];
        const float dA_t = sb[193];
        const float xv = sb[p];
        const float coef = dt_t * xv;
        const float* sB = sb + 64 + n0;
        const float* sC = sb + 128 + n0;
        float acc = 0.f;
#pragma unroll
        for (int i = 0; i < 8; i++) {
            hreg[i] = hreg[i] * dA_t + coef * sB[i];
            acc += hreg[i] * sC[i];
        }
        acc += __shfl_xor_sync(0xffffffffu, acc, 1);
        acc += __shfl_xor_sync(0xffffffffu, acc, 2);
        acc += __shfl_xor_sync(0xffffffffu, acc, 4);
        if (ng == 0) ybase[(size_t)t * D_INNER + p] = acc + Dh * xv;
    }
}

// ---------------- gate with silu(z) + RMSNorm (in-place on g_y) ----------------
__global__ void __launch_bounds__(256) norm_kernel(const float* __restrict__ norm_w) {
    const int row = blockIdx.x;
    const int tid = threadIdx.x;
    const float* zrow = g_zxbcdt + (size_t)row * D_IN_PROJ;
    float* yrow = g_y + (size_t)row * D_INNER;

    float vals[6];
    float ss = 0.f;
#pragma unroll
    for (int i = 0; i < 6; i++) {
        int c = tid + i * 256;
        float z = zrow[c];
        float yv = yrow[c] * (z / (1.f + expf(-z)));
        vals[i] = yv;
        ss += yv * yv;
    }
#pragma unroll
    for (int o = 16; o; o >>= 1) ss += __shfl_xor_sync(0xffffffffu, ss, o);
    __shared__ float red[8];
    if ((tid & 31) == 0) red[tid >> 5] = ss;
    __syncthreads();
    if (tid < 8) {
        float v = red[tid];
#pragma unroll
        for (int o = 4; o; o >>= 1) v += __shfl_xor_sync(0xffu, v, o);
        if (tid == 0) red[0] = v;
    }
    __syncthreads();
    const float scale = rsqrtf(red[0] * (1.f / D_INNER) + 1e-5f);
#pragma unroll
    for (int i = 0; i < 6; i++) {
        int c = tid + i * 256;
        yrow[c] = vals[i] * scale * norm_w[c];
    }
}

// ---------------- launch ----------------
extern "C" void kernel_launch(void* const* d_in, const int* in_sizes, int n_in,
                              void* d_out, int out_size) {
    const float* x       = (const float*)d_in[0];
    const float* W_in    = (const float*)d_in[1];
    const float* conv_w  = (const float*)d_in[2];
    const float* conv_b  = (const float*)d_in[3];
    const float* dt_bias = (const float*)d_in[4];
    const float* A_log   = (const float*)d_in[5];
    const float* Dp      = (const float*)d_in[6];
    const float* norm_w  = (const float*)d_in[7];
    const float* W_out   = (const float*)d_in[8];
    float* out = (float*)d_out;

    float *zx_ptr, *y_ptr;
    cudaGetSymbolAddress((void**)&zx_ptr, g_zxbcdt);
    cudaGetSymbolAddress((void**)&y_ptr, g_y);

    // 1) zxbcdt = x @ W_in   [8192 x 3224]
    sgemm128<<<dim3((D_IN_PROJ + 127) / 128, ROWS / 128), 256>>>(
        x, W_in, zx_ptr, ROWS, D_IN_PROJ, D_MODEL);

    // 2) dt / dA
    dt_kernel<<<(ROWS * NHEADS + 255) / 256, 256>>>(dt_bias, A_log);

    // 3) depthwise conv + silu
    conv_kernel<<<((size_t)ROWS * CONV_DIM + 255) / 256, 256>>>(conv_w, conv_b);

    // 4) sequential SSM scan
    scan_kernel<<<BATCH * NHEADS, 512>>>(Dp);

    // 5) gate + RMSNorm
    norm_kernel<<<ROWS, 256>>>(norm_w);

    // 6) out = y @ W_out    [8192 x 768]
    sgemm128<<<dim3(D_MODEL / 128, ROWS / 128), 256>>>(
        y_ptr, W_out, out, ROWS, D_MODEL, D_INNER);
}

// round 2
// speedup vs baseline: 1.6869x; 1.6869x over previous
#include <cuda_runtime.h>
#include <math.h>

#define D_MODEL   768
#define D_STATE   64
#define D_CONV    4
#define HEADDIM   64
#define D_INNER   1536
#define NHEADS    24
#define CONV_DIM  1664          // D_INNER + 2*D_STATE
#define D_IN_PROJ 3224          // 2*D_INNER + 2*D_STATE + NHEADS
#define BATCH     2
#define SEQLEN    4096
#define ROWS      (BATCH*SEQLEN)   // 8192

// ---------------- scratch (device globals; no allocation) ----------------
__device__ float g_zxbcdt[(size_t)ROWS * D_IN_PROJ];
__device__ float g_xBC[(size_t)ROWS * CONV_DIM];
__device__ float g_y[(size_t)ROWS * D_INNER];
__device__ float g_dt[ROWS * NHEADS];
__device__ float g_dA[ROWS * NHEADS];

// ---------------- 128x128x16 fp32 SGEMM, double-buffered smem ----------------
// C[M,N] = A[M,K] @ B[K,N], row-major. Requires M%128==0, K%16==0, N%8==0.
#define KS 16
__global__ void __launch_bounds__(256) sgemm_db(const float* __restrict__ A,
                                                const float* __restrict__ B,
                                                float* __restrict__ C,
                                                int M, int N, int K) {
    __shared__ __align__(16) float As[2][KS][128];
    __shared__ __align__(16) float Bs[2][KS][128];
    const int tid = threadIdx.x;
    const int tx = tid & 15;
    const int ty = tid >> 4;
    const int blockRow = blockIdx.y * 128;
    const int blockCol = blockIdx.x * 128;

    // A: 128 rows x 16 cols = 512 float4; 2 per thread
    const int aRowBase = tid >> 2;          // + i*64
    const int aC4 = (tid & 3) * 4;
    // B: 16 rows x 128 cols = 512 float4; 2 per thread
    const int bRowBase = tid >> 5;          // + i*8
    const int bCol = (tid & 31) * 4;
    const int gCol = blockCol + bCol;

    float4 ra[2], rb[2];

    float acc[8][8];
#pragma unroll
    for (int i = 0; i < 8; i++)
#pragma unroll
        for (int j = 0; j < 8; j++) acc[i][j] = 0.f;

    // prologue: load tile 0
#pragma unroll
    for (int i = 0; i < 2; i++) {
        ra[i] = *(const float4*)(A + (size_t)(blockRow + aRowBase + i * 64) * K + aC4);
        rb[i] = (gCol < N) ? *(const float4*)(B + (size_t)(bRowBase + i * 8) * N + gCol)
                           : make_float4(0.f, 0.f, 0.f, 0.f);
    }
#pragma unroll
    for (int i = 0; i < 2; i++) {
        const int r = aRowBase + i * 64;
        As[0][aC4 + 0][r] = ra[i].x;
        As[0][aC4 + 1][r] = ra[i].y;
        As[0][aC4 + 2][r] = ra[i].z;
        As[0][aC4 + 3][r] = ra[i].w;
        *(float4*)&Bs[0][bRowBase + i * 8][bCol] = rb[i];
    }
    __syncthreads();

    int buf = 0;
    for (int k0 = KS; k0 < K; k0 += KS) {
        // prefetch next tile into registers
#pragma unroll
        for (int i = 0; i < 2; i++) {
            ra[i] = *(const float4*)(A + (size_t)(blockRow + aRowBase + i * 64) * K + k0 + aC4);
            rb[i] = (gCol < N) ? *(const float4*)(B + (size_t)(k0 + bRowBase + i * 8) * N + gCol)
                               : make_float4(0.f, 0.f, 0.f, 0.f);
        }
        // compute current buffer
#pragma unroll
        for (int kk = 0; kk < KS; kk++) {
            float a[8], b[8];
            *(float4*)&a[0] = *(const float4*)&As[buf][kk][ty * 8];
            *(float4*)&a[4] = *(const float4*)&As[buf][kk][ty * 8 + 4];
            *(float4*)&b[0] = *(const float4*)&Bs[buf][kk][tx * 8];
            *(float4*)&b[4] = *(const float4*)&Bs[buf][kk][tx * 8 + 4];
#pragma unroll
            for (int i = 0; i < 8; i++)
#pragma unroll
                for (int j = 0; j < 8; j++)
                    acc[i][j] += a[i] * b[j];
        }
        // store prefetched tile into other buffer
        const int nb = buf ^ 1;
#pragma unroll
        for (int i = 0; i < 2; i++) {
            const int r = aRowBase + i * 64;
            As[nb][aC4 + 0][r] = ra[i].x;
            As[nb][aC4 + 1][r] = ra[i].y;
            As[nb][aC4 + 2][r] = ra[i].z;
            As[nb][aC4 + 3][r] = ra[i].w;
            *(float4*)&Bs[nb][bRowBase + i * 8][bCol] = rb[i];
        }
        __syncthreads();
        buf = nb;
    }
    // epilogue tile
#pragma unroll
    for (int kk = 0; kk < KS; kk++) {
        float a[8], b[8];
        *(float4*)&a[0] = *(const float4*)&As[buf][kk][ty * 8];
        *(float4*)&a[4] = *(const float4*)&As[buf][kk][ty * 8 + 4];
        *(float4*)&b[0] = *(const float4*)&Bs[buf][kk][tx * 8];
        *(float4*)&b[4] = *(const float4*)&Bs[buf][kk][tx * 8 + 4];
#pragma unroll
        for (int i = 0; i < 8; i++)
#pragma unroll
            for (int j = 0; j < 8; j++)
                acc[i][j] += a[i] * b[j];
    }

    const int colbase = blockCol + tx * 8;
    if (colbase < N) {
#pragma unroll
        for (int i = 0; i < 8; i++) {
            float* Cp = C + (size_t)(blockRow + ty * 8 + i) * N + colbase;
            *(float4*)(Cp + 0) = *(float4*)&acc[i][0];
            *(float4*)(Cp + 4) = *(float4*)&acc[i][4];
        }
    }
}

// ---------------- dt = softplus(raw + bias); dA = exp(dt * A) ----------------
__global__ void dt_kernel(const float* __restrict__ dt_bias,
                          const float* __restrict__ A_log) {
    int idx = blockIdx.x * blockDim.x + threadIdx.x;
    if (idx >= ROWS * NHEADS) return;
    int h = idx % NHEADS;
    int row = idx / NHEADS;
    float v = g_zxbcdt[(size_t)row * D_IN_PROJ + (D_INNER + CONV_DIM) + h] + dt_bias[h];
    float dtv = (v > 20.f) ? v : log1pf(expf(v));
    float A = -expf(A_log[h]);
    g_dt[idx] = dtv;
    g_dA[idx] = expf(dtv * A);
}

// ---------------- causal depthwise conv (width 4) + bias + silu ----------------
__global__ void conv_kernel(const float* __restrict__ conv_w,
                            const float* __restrict__ conv_b) {
    int idx = blockIdx.x * blockDim.x + threadIdx.x;
    if (idx >= ROWS * CONV_DIM) return;
    int c = idx % CONV_DIM;
    int row = idx / CONV_DIM;
    int l = row & (SEQLEN - 1);
    float acc = conv_b[c];
#pragma unroll
    for (int k = 0; k < D_CONV; k++) {
        int ls = l + k - (D_CONV - 1);
        if (ls >= 0)
            acc += g_zxbcdt[(size_t)(row + k - (D_CONV - 1)) * D_IN_PROJ + D_INNER + c] *
                   conv_w[c * D_CONV + k];
    }
    g_xBC[idx] = acc / (1.f + expf(-acc));
}

// ---------------- sequential SSM scan ----------------
// HEADDIM split 4-ways across blocks (p-lanes independent given shared B,C).
// Grid = BATCH*NHEADS*4 = 192 blocks, 256 threads.
// Thread map: p_loc = tid>>4 (0..15), sub = tid&15, n0 = sub*4 (4 state cols each).
// 4-deep register prefetch queue + double-buffered smem, one barrier/step.
#define PSPLIT 4
#define P_PER  (HEADDIM / PSPLIT)   // 16
__global__ void __launch_bounds__(256) scan_kernel(const float* __restrict__ Dparam) {
    __shared__ __align__(16) float sbuf[2][148];  // x[0..15] B[16..79] C[80..143] dt=144 dA=145
    const int tid = threadIdx.x;
    const int blk = blockIdx.x;
    const int bh = blk / PSPLIT;
    const int ps = blk % PSPLIT;
    const int b = bh / NHEADS, h = bh % NHEADS;
    const int p0 = ps * P_PER;
    const int p_loc = tid >> 4;
    const int sub = tid & 15;
    const int n0 = sub * 4;

    float hreg[4] = {0.f, 0.f, 0.f, 0.f};
    const float Dh = Dparam[h];

    const float* xbase  = g_xBC + (size_t)b * SEQLEN * CONV_DIM;
    const float* dtbase = g_dt + (size_t)b * SEQLEN * NHEADS + h;
    const float* dAbase = g_dA + (size_t)b * SEQLEN * NHEADS + h;
    float*       ybase  = g_y + (size_t)b * SEQLEN * D_INNER + h * HEADDIM + p0;

    // per-thread load of one value for timestep t
    auto ld = [&](int t) -> float {
        const float* rowp = xbase + (size_t)t * CONV_DIM;
        if (tid < 16)   return rowp[h * HEADDIM + p0 + tid];
        if (tid < 80)   return rowp[D_INNER + (tid - 16)];
        if (tid < 144)  return rowp[D_INNER + D_STATE + (tid - 80)];
        if (tid == 144) return dtbase[(size_t)t * NHEADS];
        if (tid == 145) return dAbase[(size_t)t * NHEADS];
        return 0.f;
    };

    float q0 = ld(0), q1 = ld(1), q2 = ld(2), q3 = ld(3);
    if (tid < 146) sbuf[0][tid] = q0;
    q0 = q1; q1 = q2; q2 = q3;
    __syncthreads();

    for (int t = 0; t < SEQLEN; t++) {
        // stage data for t+1 into the other buffer (readers of it finished at t-1's barrier)
        if (tid < 146) sbuf[(t + 1) & 1][tid] = q0;
        q0 = q1; q1 = q2;
        q2 = (t + 4 < SEQLEN) ? ld(t + 4) : 0.f;

        const float* sb = sbuf[t & 1];
        const float dt_t = sb[144];
        const float dA_t = sb[145];
        const float xv = sb[p_loc];
        const float coef = dt_t * xv;
        const float4 Bv = *(const float4*)&sb[16 + n0];
        const float4 Cv = *(const float4*)&sb[80 + n0];

        float acc;
        hreg[0] = hreg[0] * dA_t + coef * Bv.x; acc  = hreg[0] * Cv.x;
        hreg[1] = hreg[1] * dA_t + coef * Bv.y; acc += hreg[1] * Cv.y;
        hreg[2] = hreg[2] * dA_t + coef * Bv.z; acc += hreg[2] * Cv.z;
        hreg[3] = hreg[3] * dA_t + coef * Bv.w; acc += hreg[3] * Cv.w;

        acc += __shfl_xor_sync(0xffffffffu, acc, 1);
        acc += __shfl_xor_sync(0xffffffffu, acc, 2);
        acc += __shfl_xor_sync(0xffffffffu, acc, 4);
        acc += __shfl_xor_sync(0xffffffffu, acc, 8);
        if (sub == 0) ybase[(size_t)t * D_INNER + p_loc] = acc + Dh * xv;
        __syncthreads();
    }
}

// ---------------- gate with silu(z) + RMSNorm (in-place on g_y) ----------------
__global__ void __launch_bounds__(256) norm_kernel(const float* __restrict__ norm_w) {
    const int row = blockIdx.x;
    const int tid = threadIdx.x;
    const float* zrow = g_zxbcdt + (size_t)row * D_IN_PROJ;
    float* yrow = g_y + (size_t)row * D_INNER;

    float vals[6];
    float ss = 0.f;
#pragma unroll
    for (int i = 0; i < 6; i++) {
        int c = tid + i * 256;
        float z = zrow[c];
        float yv = yrow[c] * (z / (1.f + expf(-z)));
        vals[i] = yv;
        ss += yv * yv;
    }
#pragma unroll
    for (int o = 16; o; o >>= 1) ss += __shfl_xor_sync(0xffffffffu, ss, o);
    __shared__ float red[8];
    if ((tid & 31) == 0) red[tid >> 5] = ss;
    __syncthreads();
    if (tid < 8) {
        float v = red[tid];
#pragma unroll
        for (int o = 4; o; o >>= 1) v += __shfl_xor_sync(0xffu, v, o);
        if (tid == 0) red[0] = v;
    }
    __syncthreads();
    const float scale = rsqrtf(red[0] * (1.f / D_INNER) + 1e-5f);
#pragma unroll
    for (int i = 0; i < 6; i++) {
        int c = tid + i * 256;
        yrow[c] = vals[i] * scale * norm_w[c];
    }
}

// ---------------- launch ----------------
extern "C" void kernel_launch(void* const* d_in, const int* in_sizes, int n_in,
                              void* d_out, int out_size) {
    const float* x       = (const float*)d_in[0];
    const float* W_in    = (const float*)d_in[1];
    const float* conv_w  = (const float*)d_in[2];
    const float* conv_b  = (const float*)d_in[3];
    const float* dt_bias = (const float*)d_in[4];
    const float* A_log   = (const float*)d_in[5];
    const float* Dp      = (const float*)d_in[6];
    const float* norm_w  = (const float*)d_in[7];
    const float* W_out   = (const float*)d_in[8];
    float* out = (float*)d_out;

    float *zx_ptr, *y_ptr;
    cudaGetSymbolAddress((void**)&zx_ptr, g_zxbcdt);
    cudaGetSymbolAddress((void**)&y_ptr, g_y);

    // 1) zxbcdt = x @ W_in   [8192 x 3224]
    sgemm_db<<<dim3((D_IN_PROJ + 127) / 128, ROWS / 128), 256>>>(
        x, W_in, zx_ptr, ROWS, D_IN_PROJ, D_MODEL);

    // 2) dt / dA
    dt_kernel<<<(ROWS * NHEADS + 255) / 256, 256>>>(dt_bias, A_log);

    // 3) depthwise conv + silu
    conv_kernel<<<((size_t)ROWS * CONV_DIM + 255) / 256, 256>>>(conv_w, conv_b);

    // 4) sequential SSM scan (HEADDIM split 4-ways)
    scan_kernel<<<BATCH * NHEADS * PSPLIT, 256>>>(Dp);

    // 5) gate + RMSNorm
    norm_kernel<<<ROWS, 256>>>(norm_w);

    // 6) out = y @ W_out    [8192 x 768]
    sgemm_db<<<dim3(D_MODEL / 128, ROWS / 128), 256>>>(
        y_ptr, W_out, out, ROWS, D_MODEL, D_INNER);
}

// round 4
// speedup vs baseline: 2.2588x; 1.3390x over previous
#include <cuda_runtime.h>
#include <cuda_bf16.h>
#include <math.h>
#include <stdint.h>

#define D_MODEL   768
#define D_STATE   64
#define D_CONV    4
#define HEADDIM   64
#define D_INNER   1536
#define NHEADS    24
#define CONV_DIM  1664
#define D_IN_PROJ 3224
#define BATCH     2
#define SEQLEN    4096
#define ROWS      (BATCH*SEQLEN)
#define NPAD1     3328            // D_IN_PROJ padded to 128

// ---------------- scratch (device globals; no allocation) ----------------
__device__ float g_zxbcdt[(size_t)ROWS * D_IN_PROJ];
__device__ float g_xBC[(size_t)ROWS * CONV_DIM];
__device__ float g_y[(size_t)ROWS * D_INNER];
__device__ float g_dt[ROWS * NHEADS];
__device__ float g_dA[ROWS * NHEADS];
__device__ __nv_bfloat16 g_xhi[(size_t)ROWS * D_MODEL];
__device__ __nv_bfloat16 g_xlo[(size_t)ROWS * D_MODEL];
__device__ __nv_bfloat16 g_yhi[(size_t)ROWS * D_INNER];
__device__ __nv_bfloat16 g_ylo[(size_t)ROWS * D_INNER];
__device__ __nv_bfloat16 g_wi_hi[(size_t)NPAD1 * D_MODEL];   // W_in^T  [3328 x 768]
__device__ __nv_bfloat16 g_wi_lo[(size_t)NPAD1 * D_MODEL];
__device__ __nv_bfloat16 g_wo_hi[(size_t)D_MODEL * D_INNER]; // W_out^T [768 x 1536]
__device__ __nv_bfloat16 g_wo_lo[(size_t)D_MODEL * D_INNER];

// ---------------- warp-MMA bf16-split GEMM ----------------
// C[M,N] = sum_k A[m,k]*B_t[n,k]; A row-major [M,K] (hi/lo), B_t row-major [Npad,K] (hi/lo).
// Block 128x128, 8 warps (4m x 2n), warp tile 32x64, K-chunk 32, cp.async double buffer.
#define KC     32
#define APITCH 40                    // bf16 elems per smem row (80B, 16B aligned, conflict-free)
#define TILE_E (128 * APITCH)        // elems per array tile
#define BUF_E  (4 * TILE_E)          // Ahi,Alo,Bhi,Blo
#define GSMEM  (2 * BUF_E * 2)       // bytes: 81920

__device__ __forceinline__ void cp16(uint32_t dst, const void* src) {
    asm volatile("cp.async.ca.shared.global [%0], [%1], 16;" :: "r"(dst), "l"(src) : "memory");
}
__device__ __forceinline__ void cp_commit() {
    asm volatile("cp.async.commit_group;" ::: "memory");
}
template <int N> __device__ __forceinline__ void cp_wait() {
    asm volatile("cp.async.wait_group %0;" :: "n"(N) : "memory");
}
__device__ __forceinline__ void mma_bf16(float* d, const uint32_t* a, uint32_t b0, uint32_t b1) {
    asm volatile("mma.sync.aligned.m16n8k16.row.col.f32.bf16.bf16.f32 "
                 "{%0,%1,%2,%3}, {%4,%5,%6,%7}, {%8,%9}, {%0,%1,%2,%3};"
                 : "+f"(d[0]), "+f"(d[1]), "+f"(d[2]), "+f"(d[3])
                 : "r"(a[0]), "r"(a[1]), "r"(a[2]), "r"(a[3]), "r"(b0), "r"(b1));
}

__global__ void __launch_bounds__(256) mma_gemm(
    const __nv_bfloat16* __restrict__ Ahi, const __nv_bfloat16* __restrict__ Alo,
    const __nv_bfloat16* __restrict__ Bhi, const __nv_bfloat16* __restrict__ Blo,
    float* __restrict__ C, int M, int N, int K) {
    extern __shared__ __nv_bfloat16 sm[];
    const int tid = threadIdx.x;
    const int wid = tid >> 5, lane = tid & 31;
    const int warp_m = wid >> 1, warp_n = wid & 1;
    const int g = lane >> 2, tig = lane & 3;
    const int bm = blockIdx.y * 128, bn = blockIdx.x * 128;

    const uint32_t sbase = (uint32_t)__cvta_generic_to_shared(sm);

    float acc[2][8][4];
#pragma unroll
    for (int mt = 0; mt < 2; mt++)
#pragma unroll
        for (int nt = 0; nt < 8; nt++)
#pragma unroll
            for (int i = 0; i < 4; i++) acc[mt][nt][i] = 0.f;

    const int nkt = K / KC;

    auto issue = [&](int kt) {
        const int buf = kt & 1;
        const int kofs = kt * KC;
        const __nv_bfloat16* srcs[4] = {Ahi, Alo, Bhi, Blo};
#pragma unroll
        for (int arr = 0; arr < 4; arr++) {
            const int rbase = (arr < 2) ? bm : bn;
            const uint32_t dbase = sbase + (uint32_t)(buf * BUF_E + arr * TILE_E) * 2;
#pragma unroll
            for (int i = 0; i < 2; i++) {
                const int u = tid + i * 256;      // 0..511
                const int r = u >> 2, seg = u & 3;
                cp16(dbase + (uint32_t)(r * APITCH + seg * 8) * 2,
                     srcs[arr] + (size_t)(rbase + r) * K + kofs + seg * 8);
            }
        }
    };

    issue(0); cp_commit();
    if (nkt > 1) { issue(1); cp_commit(); }

    for (int kt = 0; kt < nkt; kt++) {
        if (kt + 1 < nkt) cp_wait<1>(); else cp_wait<0>();
        __syncthreads();

        const __nv_bfloat16* base = sm + (kt & 1) * BUF_E;
        const __nv_bfloat16* sAhi = base;
        const __nv_bfloat16* sAlo = base + TILE_E;
        const __nv_bfloat16* sBhi = base + 2 * TILE_E;
        const __nv_bfloat16* sBlo = base + 3 * TILE_E;

#pragma unroll
        for (int ks = 0; ks < KC; ks += 16) {
            uint32_t afh[2][4], afl[2][4];
#pragma unroll
            for (int mt = 0; mt < 2; mt++) {
                const int row = warp_m * 32 + mt * 16 + g;
                const int c0 = ks + 2 * tig;
                afh[mt][0] = *(const uint32_t*)&sAhi[row * APITCH + c0];
                afh[mt][1] = *(const uint32_t*)&sAhi[(row + 8) * APITCH + c0];
                afh[mt][2] = *(const uint32_t*)&sAhi[row * APITCH + c0 + 8];
                afh[mt][3] = *(const uint32_t*)&sAhi[(row + 8) * APITCH + c0 + 8];
                afl[mt][0] = *(const uint32_t*)&sAlo[row * APITCH + c0];
                afl[mt][1] = *(const uint32_t*)&sAlo[(row + 8) * APITCH + c0];
                afl[mt][2] = *(const uint32_t*)&sAlo[row * APITCH + c0 + 8];
                afl[mt][3] = *(const uint32_t*)&sAlo[(row + 8) * APITCH + c0 + 8];
            }
#pragma unroll
            for (int nt = 0; nt < 8; nt++) {
                const int nrow = warp_n * 64 + nt * 8 + g;
                const int c0 = ks + 2 * tig;
                const uint32_t bh0 = *(const uint32_t*)&sBhi[nrow * APITCH + c0];
                const uint32_t bh1 = *(const uint32_t*)&sBhi[nrow * APITCH + c0 + 8];
                const uint32_t bl0 = *(const uint32_t*)&sBlo[nrow * APITCH + c0];
                const uint32_t bl1 = *(const uint32_t*)&sBlo[nrow * APITCH + c0 + 8];
#pragma unroll
                for (int mt = 0; mt < 2; mt++) {
                    mma_bf16(acc[mt][nt], afh[mt], bh0, bh1);
                    mma_bf16(acc[mt][nt], afh[mt], bl0, bl1);
                    mma_bf16(acc[mt][nt], afl[mt], bh0, bh1);
                }
            }
        }
        __syncthreads();
        if (kt + 2 < nkt) { issue(kt + 2); cp_commit(); }
    }

    // epilogue
#pragma unroll
    for (int mt = 0; mt < 2; mt++) {
        const int row0 = bm + warp_m * 32 + mt * 16 + g;
#pragma unroll
        for (int nt = 0; nt < 8; nt++) {
            const int col = bn + warp_n * 64 + nt * 8 + 2 * tig;
            if (col < N) {   // N even, col even -> col+1 < N too
                *(float2*)&C[(size_t)row0 * N + col] = make_float2(acc[mt][nt][0], acc[mt][nt][1]);
                *(float2*)&C[(size_t)(row0 + 8) * N + col] = make_float2(acc[mt][nt][2], acc[mt][nt][3]);
            }
        }
    }
}

// ---------------- fp32 -> bf16 hi/lo split (elementwise) ----------------
__global__ void convert_split(const float* __restrict__ src,
                              __nv_bfloat16* __restrict__ hi,
                              __nv_bfloat16* __restrict__ lo, int n4) {
    int i = blockIdx.x * blockDim.x + threadIdx.x;
    if (i >= n4) return;
    const int idx = i * 4;
    float4 v = *(const float4*)(src + idx);
    __nv_bfloat16 h[4], l[4];
    h[0] = __float2bfloat16(v.x); l[0] = __float2bfloat16(v.x - __bfloat162float(h[0]));
    h[1] = __float2bfloat16(v.y); l[1] = __float2bfloat16(v.y - __bfloat162float(h[1]));
    h[2] = __float2bfloat16(v.z); l[2] = __float2bfloat16(v.z - __bfloat162float(h[2]));
    h[3] = __float2bfloat16(v.w); l[3] = __float2bfloat16(v.w - __bfloat162float(h[3]));
    *(uint2*)(hi + idx) = *(uint2*)h;
    *(uint2*)(lo + idx) = *(uint2*)l;
}

// ---------------- transpose + split: src[R x C] -> out[Cpad x R] bf16 hi/lo ----------------
__global__ void transpose_split(const float* __restrict__ src,
                                __nv_bfloat16* __restrict__ hi,
                                __nv_bfloat16* __restrict__ lo,
                                int R, int C, int Cpad) {
    __shared__ float tile[32][33];
    const int c0 = blockIdx.x * 32, r0 = blockIdx.y * 32;
    const int tx = threadIdx.x, ty = threadIdx.y;
    const int c = c0 + tx;
#pragma unroll
    for (int j = ty; j < 32; j += 8) {
        const int r = r0 + j;
        tile[j][tx] = (r < R && c < C) ? src[(size_t)r * C + c] : 0.f;
    }
    __syncthreads();
#pragma unroll
    for (int j = ty; j < 32; j += 8) {
        const int orow = c0 + j;
        const int ocol = r0 + tx;
        if (orow < Cpad && ocol < R) {
            float v = tile[tx][j];
            __nv_bfloat16 h = __float2bfloat16(v);
            hi[(size_t)orow * R + ocol] = h;
            lo[(size_t)orow * R + ocol] = __float2bfloat16(v - __bfloat162float(h));
        }
    }
}

// ---------------- dt = softplus(raw + bias); dA = exp(dt * A) ----------------
__global__ void dt_kernel(const float* __restrict__ dt_bias,
                          const float* __restrict__ A_log) {
    int idx = blockIdx.x * blockDim.x + threadIdx.x;
    if (idx >= ROWS * NHEADS) return;
    int h = idx % NHEADS;
    int row = idx / NHEADS;
    float v = g_zxbcdt[(size_t)row * D_IN_PROJ + (D_INNER + CONV_DIM) + h] + dt_bias[h];
    float dtv = (v > 20.f) ? v : log1pf(expf(v));
    float A = -expf(A_log[h]);
    g_dt[idx] = dtv;
    g_dA[idx] = expf(dtv * A);
}

// ---------------- causal depthwise conv (width 4) + bias + silu ----------------
__global__ void conv_kernel(const float* __restrict__ conv_w,
                            const float* __restrict__ conv_b) {
    int idx = blockIdx.x * blockDim.x + threadIdx.x;
    if (idx >= ROWS * CONV_DIM) return;
    int c = idx % CONV_DIM;
    int row = idx / CONV_DIM;
    int l = row & (SEQLEN - 1);
    float acc = conv_b[c];
#pragma unroll
    for (int k = 0; k < D_CONV; k++) {
        int ls = l + k - (D_CONV - 1);
        if (ls >= 0)
            acc += g_zxbcdt[(size_t)(row + k - (D_CONV - 1)) * D_IN_PROJ + D_INNER + c] *
                   conv_w[c * D_CONV + k];
    }
    g_xBC[idx] = acc / (1.f + expf(-acc));
}

// ---------------- sequential SSM scan (HEADDIM split 4-ways) ----------------
#define PSPLIT 4
#define P_PER  (HEADDIM / PSPLIT)
__global__ void __launch_bounds__(256) scan_kernel(const float* __restrict__ Dparam) {
    __shared__ __align__(16) float sbuf[2][148];
    const int tid = threadIdx.x;
    const int blk = blockIdx.x;
    const int bh = blk / PSPLIT;
    const int ps = blk % PSPLIT;
    const int b = bh / NHEADS, h = bh % NHEADS;
    const int p0 = ps * P_PER;
    const int p_loc = tid >> 4;
    const int sub = tid & 15;
    const int n0 = sub * 4;

    float hreg[4] = {0.f, 0.f, 0.f, 0.f};
    const float Dh = Dparam[h];

    const float* xbase  = g_xBC + (size_t)b * SEQLEN * CONV_DIM;
    const float* dtbase = g_dt + (size_t)b * SEQLEN * NHEADS + h;
    const float* dAbase = g_dA + (size_t)b * SEQLEN * NHEADS + h;
    float*       ybase  = g_y + (size_t)b * SEQLEN * D_INNER + h * HEADDIM + p0;

    auto ld = [&](int t) -> float {
        const float* rowp = xbase + (size_t)t * CONV_DIM;
        if (tid < 16)   return rowp[h * HEADDIM + p0 + tid];
        if (tid < 80)   return rowp[D_INNER + (tid - 16)];
        if (tid < 144)  return rowp[D_INNER + D_STATE + (tid - 80)];
        if (tid == 144) return dtbase[(size_t)t * NHEADS];
        if (tid == 145) return dAbase[(size_t)t * NHEADS];
        return 0.f;
    };

    float q0 = ld(0), q1 = ld(1), q2 = ld(2), q3 = ld(3);
    if (tid < 146) sbuf[0][tid] = q0;
    q0 = q1; q1 = q2; q2 = q3;
    __syncthreads();

    for (int t = 0; t < SEQLEN; t++) {
        if (tid < 146) sbuf[(t + 1) & 1][tid] = q0;
        q0 = q1; q1 = q2;
        q2 = (t + 4 < SEQLEN) ? ld(t + 4) : 0.f;

        const float* sb = sbuf[t & 1];
        const float dt_t = sb[144];
        const float dA_t = sb[145];
        const float xv = sb[p_loc];
        const float coef = dt_t * xv;
        const float4 Bv = *(const float4*)&sb[16 + n0];
        const float4 Cv = *(const float4*)&sb[80 + n0];

        float acc;
        hreg[0] = hreg[0] * dA_t + coef * Bv.x; acc  = hreg[0] * Cv.x;
        hreg[1] = hreg[1] * dA_t + coef * Bv.y; acc += hreg[1] * Cv.y;
        hreg[2] = hreg[2] * dA_t + coef * Bv.z; acc += hreg[2] * Cv.z;
        hreg[3] = hreg[3] * dA_t + coef * Bv.w; acc += hreg[3] * Cv.w;

        acc += __shfl_xor_sync(0xffffffffu, acc, 1);
        acc += __shfl_xor_sync(0xffffffffu, acc, 2);
        acc += __shfl_xor_sync(0xffffffffu, acc, 4);
        acc += __shfl_xor_sync(0xffffffffu, acc, 8);
        if (sub == 0) ybase[(size_t)t * D_INNER + p_loc] = acc + Dh * xv;
        __syncthreads();
    }
}

// ---------------- gate with silu(z) + RMSNorm (in-place on g_y) ----------------
__global__ void __launch_bounds__(256) norm_kernel(const float* __restrict__ norm_w) {
    const int row = blockIdx.x;
    const int tid = threadIdx.x;
    const float* zrow = g_zxbcdt + (size_t)row * D_IN_PROJ;
    float* yrow = g_y + (size_t)row * D_INNER;

    float vals[6];
    float ss = 0.f;
#pragma unroll
    for (int i = 0; i < 6; i++) {
        int c = tid + i * 256;
        float z = zrow[c];
        float yv = yrow[c] * (z / (1.f + expf(-z)));
        vals[i] = yv;
        ss += yv * yv;
    }
#pragma unroll
    for (int o = 16; o; o >>= 1) ss += __shfl_xor_sync(0xffffffffu, ss, o);
    __shared__ float red[8];
    if ((tid & 31) == 0) red[tid >> 5] = ss;
    __syncthreads();
    if (tid < 8) {
        float v = red[tid];
#pragma unroll
        for (int o = 4; o; o >>= 1) v += __shfl_xor_sync(0xffu, v, o);
        if (tid == 0) red[0] = v;
    }
    __syncthreads();
    const float scale = rsqrtf(red[0] * (1.f / D_INNER) + 1e-5f);
#pragma unroll
    for (int i = 0; i < 6; i++) {
        int c = tid + i * 256;
        yrow[c] = vals[i] * scale * norm_w[c];
    }
}

// ---------------- launch ----------------
extern "C" void kernel_launch(void* const* d_in, const int* in_sizes, int n_in,
                              void* d_out, int out_size) {
    const float* x       = (const float*)d_in[0];
    const float* W_in    = (const float*)d_in[1];
    const float* conv_w  = (const float*)d_in[2];
    const float* conv_b  = (const float*)d_in[3];
    const float* dt_bias = (const float*)d_in[4];
    const float* A_log   = (const float*)d_in[5];
    const float* Dp      = (const float*)d_in[6];
    const float* norm_w  = (const float*)d_in[7];
    const float* W_out   = (const float*)d_in[8];
    float* out = (float*)d_out;

    float *zx_ptr, *y_ptr;
    cudaGetSymbolAddress((void**)&zx_ptr, g_zxbcdt);
    cudaGetSymbolAddress((void**)&y_ptr, g_y);
    __nv_bfloat16 *xhi, *xlo, *yhi, *ylo, *wihi, *wilo, *wohi, *wolo;
    cudaGetSymbolAddress((void**)&xhi, g_xhi);
    cudaGetSymbolAddress((void**)&xlo, g_xlo);
    cudaGetSymbolAddress((void**)&yhi, g_yhi);
    cudaGetSymbolAddress((void**)&ylo, g_ylo);
    cudaGetSymbolAddress((void**)&wihi, g_wi_hi);
    cudaGetSymbolAddress((void**)&wilo, g_wi_lo);
    cudaGetSymbolAddress((void**)&wohi, g_wo_hi);
    cudaGetSymbolAddress((void**)&wolo, g_wo_lo);

    static int smem_set = 0;
    if (!smem_set) {
        cudaFuncSetAttribute(mma_gemm, cudaFuncAttributeMaxDynamicSharedMemorySize, GSMEM);
        smem_set = 1;
    }

    // 1) split x; transpose+split W_in
    convert_split<<<(ROWS * D_MODEL / 4 + 255) / 256, 256>>>(x, xhi, xlo, ROWS * D_MODEL / 4);
    transpose_split<<<dim3(NPAD1 / 32, D_MODEL / 32), dim3(32, 8)>>>(
        W_in, wihi, wilo, D_MODEL, D_IN_PROJ, NPAD1);

    // 2) zxbcdt = x @ W_in
    mma_gemm<<<dim3(NPAD1 / 128, ROWS / 128), 256, GSMEM>>>(
        xhi, xlo, wihi, wilo, zx_ptr, ROWS, D_IN_PROJ, D_MODEL);

    // 3) dt / dA
    dt_kernel<<<(ROWS * NHEADS + 255) / 256, 256>>>(dt_bias, A_log);

    // 4) depthwise conv + silu
    conv_kernel<<<((size_t)ROWS * CONV_DIM + 255) / 256, 256>>>(conv_w, conv_b);

    // 5) sequential SSM scan
    scan_kernel<<<BATCH * NHEADS * PSPLIT, 256>>>(Dp);

    // 6) gate + RMSNorm
    norm_kernel<<<ROWS, 256>>>(norm_w);

    // 7) split y; transpose+split W_out
    convert_split<<<(ROWS * D_INNER / 4 + 255) / 256, 256>>>(y_ptr, yhi, ylo, ROWS * D_INNER / 4);
    transpose_split<<<dim3(D_MODEL / 32, D_INNER / 32), dim3(32, 8)>>>(
        W_out, wohi, wolo, D_INNER, D_MODEL, D_MODEL);

    // 8) out = y @ W_out
    mma_gemm<<<dim3(D_MODEL / 128, ROWS / 128), 256, GSMEM>>>(
        yhi, ylo, wohi, wolo, out, ROWS, D_MODEL, D_INNER);
}

// round 5
// speedup vs baseline: 2.5029x; 1.1081x over previous
#include <cuda_runtime.h>
#include <cuda_fp16.h>
#include <math.h>
#include <stdint.h>

#define D_MODEL   768
#define D_STATE   64
#define D_CONV    4
#define HEADDIM   64
#define D_INNER   1536
#define NHEADS    24
#define CONV_DIM  1664
#define D_IN_PROJ 3224
#define BATCH     2
#define SEQLEN    4096
#define ROWS      (BATCH*SEQLEN)
#define NPAD1     3328            // D_IN_PROJ padded to 128

// ---------------- scratch (device globals; no allocation) ----------------
__device__ float g_zxbcdt[(size_t)ROWS * D_IN_PROJ];
__device__ float g_xBC[(size_t)ROWS * CONV_DIM];
__device__ float g_y[(size_t)ROWS * D_INNER];
__device__ float g_dt[ROWS * NHEADS];
__device__ float g_dA[ROWS * NHEADS];
__device__ __half g_xhi[(size_t)ROWS * D_MODEL];
__device__ __half g_xlo[(size_t)ROWS * D_MODEL];
__device__ __half g_yhi[(size_t)ROWS * D_INNER];
__device__ __half g_ylo[(size_t)ROWS * D_INNER];
__device__ __half g_wi[(size_t)NPAD1 * D_MODEL];     // W_in^T  [3328 x 768] fp16
__device__ __half g_wo[(size_t)D_MODEL * D_INNER];   // W_out^T [768 x 1536] fp16

// ---------------- warp-MMA fp16 GEMM (A split hi/lo, B single) ----------------
// C[M,N] = sum_k A[m,k]*B_t[n,k]; A row-major [M,K] fp16 hi/lo, B_t row-major [Npad,K] fp16.
// Block 128x128, 8 warps (4m x 2n), warp tile 32x64, K-chunk 32, 3-stage cp.async.
#define KC      32
#define PITCH   40                      // fp16 elems per smem row (80B)
#define TILE_E  (128 * PITCH)           // 5120 elems
#define TILE_B  (TILE_E * 2)            // 10240 bytes
#define STAGE_B (3 * TILE_B)            // Ahi, Alo, B : 30720 bytes
#define STAGES  3
#define GSMEM   (STAGES * STAGE_B)      // 92160 bytes

__device__ __forceinline__ void cp16(uint32_t dst, const void* src) {
    asm volatile("cp.async.ca.shared.global [%0], [%1], 16;" :: "r"(dst), "l"(src) : "memory");
}
__device__ __forceinline__ void cp_commit() {
    asm volatile("cp.async.commit_group;" ::: "memory");
}
template <int N> __device__ __forceinline__ void cp_wait() {
    asm volatile("cp.async.wait_group %0;" :: "n"(N) : "memory");
}
__device__ __forceinline__ void ldsm4(uint32_t* r, uint32_t addr) {
    asm volatile("ldmatrix.sync.aligned.m8n8.x4.shared.b16 {%0,%1,%2,%3}, [%4];"
                 : "=r"(r[0]), "=r"(r[1]), "=r"(r[2]), "=r"(r[3]) : "r"(addr));
}
__device__ __forceinline__ void mma_f16(float* d, const uint32_t* a, uint32_t b0, uint32_t b1) {
    asm volatile("mma.sync.aligned.m16n8k16.row.col.f32.f16.f16.f32 "
                 "{%0,%1,%2,%3}, {%4,%5,%6,%7}, {%8,%9}, {%0,%1,%2,%3};"
                 : "+f"(d[0]), "+f"(d[1]), "+f"(d[2]), "+f"(d[3])
                 : "r"(a[0]), "r"(a[1]), "r"(a[2]), "r"(a[3]), "r"(b0), "r"(b1));
}

__global__ void __launch_bounds__(256, 2) mma_gemm(
    const __half* __restrict__ Ahi, const __half* __restrict__ Alo,
    const __half* __restrict__ Bh,
    float* __restrict__ C, int M, int N, int K) {
    extern __shared__ __half sm[];
    const int tid = threadIdx.x;
    const int wid = tid >> 5, lane = tid & 31;
    const int warp_m = wid >> 1, warp_n = wid & 1;
    const int g = lane >> 2, tig = lane & 3;
    const int bm = blockIdx.y * 128, bn = blockIdx.x * 128;
    const uint32_t sbase = (uint32_t)__cvta_generic_to_shared(sm);

    float acc[2][8][4];
#pragma unroll
    for (int mt = 0; mt < 2; mt++)
#pragma unroll
        for (int nt = 0; nt < 8; nt++)
#pragma unroll
            for (int i = 0; i < 4; i++) acc[mt][nt][i] = 0.f;

    const int nkt = K / KC;
    const int r_ld = tid >> 2, seg_ld = tid & 3;   // 64 rows per i-step, 4 segs

    auto issue = [&](int kt) {
        const int st = kt % STAGES;
        const int kofs = kt * KC;
        const uint32_t dst0 = sbase + st * STAGE_B;
        const __half* srcs[3] = {Ahi, Alo, Bh};
#pragma unroll
        for (int arr = 0; arr < 3; arr++) {
            const int rbase = (arr < 2) ? bm : bn;
            const uint32_t db = dst0 + arr * TILE_B;
#pragma unroll
            for (int i = 0; i < 2; i++) {
                const int r = r_ld + i * 64;
                cp16(db + (uint32_t)(r * PITCH + seg_ld * 8) * 2,
                     srcs[arr] + (size_t)(rbase + r) * K + kofs + seg_ld * 8);
            }
        }
    };

    issue(0); cp_commit();
    if (nkt > 1) { issue(1); cp_commit(); }

    // ldmatrix lane addressing (element offsets within a tile)
    const int a_row = (lane & 15);          // + warp_m*32 + mt*16
    const int a_col = (lane >> 4) * 8;      // + ks
    const int b_row = (lane & 7) + ((lane >> 4) * 8);   // + warp_n*64 + ntp*16
    const int b_col = ((lane >> 3) & 1) * 8;            // + ks

    for (int kt = 0; kt < nkt; kt++) {
        if (kt + 2 < nkt) cp_wait<1>(); else cp_wait<0>();
        __syncthreads();
        if (kt + 2 < nkt) { issue(kt + 2); cp_commit(); }

        const uint32_t st0 = sbase + (kt % STAGES) * STAGE_B;
        const uint32_t aHi = st0;
        const uint32_t aLo = st0 + TILE_B;
        const uint32_t bB  = st0 + 2 * TILE_B;

#pragma unroll
        for (int ks = 0; ks < KC; ks += 16) {
            uint32_t ah[2][4], al[2][4], bf[4][4];
#pragma unroll
            for (int mt = 0; mt < 2; mt++) {
                const uint32_t aoff =
                    (uint32_t)((warp_m * 32 + mt * 16 + a_row) * PITCH + ks + a_col) * 2;
                ldsm4(ah[mt], aHi + aoff);
                ldsm4(al[mt], aLo + aoff);
            }
#pragma unroll
            for (int ntp = 0; ntp < 4; ntp++) {
                const uint32_t boff =
                    (uint32_t)((warp_n * 64 + ntp * 16 + b_row) * PITCH + ks + b_col) * 2;
                ldsm4(bf[ntp], bB + boff);
            }
#pragma unroll
            for (int nt = 0; nt < 8; nt++) {
                const uint32_t b0 = bf[nt >> 1][(nt & 1) * 2];
                const uint32_t b1 = bf[nt >> 1][(nt & 1) * 2 + 1];
#pragma unroll
                for (int mt = 0; mt < 2; mt++) {
                    mma_f16(acc[mt][nt], ah[mt], b0, b1);
                    mma_f16(acc[mt][nt], al[mt], b0, b1);
                }
            }
        }
        __syncthreads();
    }

    // epilogue
#pragma unroll
    for (int mt = 0; mt < 2; mt++) {
        const int row0 = bm + warp_m * 32 + mt * 16 + g;
#pragma unroll
        for (int nt = 0; nt < 8; nt++) {
            const int col = bn + warp_n * 64 + nt * 8 + 2 * tig;
            if (col < N) {
                *(float2*)&C[(size_t)row0 * N + col] = make_float2(acc[mt][nt][0], acc[mt][nt][1]);
                *(float2*)&C[(size_t)(row0 + 8) * N + col] = make_float2(acc[mt][nt][2], acc[mt][nt][3]);
            }
        }
    }
}

// ---------------- fp32 -> fp16 hi/lo split (elementwise) ----------------
__global__ void convert_split(const float* __restrict__ src,
                              __half* __restrict__ hi,
                              __half* __restrict__ lo, int n4) {
    int i = blockIdx.x * blockDim.x + threadIdx.x;
    if (i >= n4) return;
    const int idx = i * 4;
    float4 v = *(const float4*)(src + idx);
    __half h[4], l[4];
    h[0] = __float2half(v.x); l[0] = __float2half(v.x - __half2float(h[0]));
    h[1] = __float2half(v.y); l[1] = __float2half(v.y - __half2float(h[1]));
    h[2] = __float2half(v.z); l[2] = __float2half(v.z - __half2float(h[2]));
    h[3] = __float2half(v.w); l[3] = __float2half(v.w - __half2float(h[3]));
    *(uint2*)(hi + idx) = *(uint2*)h;
    *(uint2*)(lo + idx) = *(uint2*)l;
}

// ---------------- transpose to fp16: src[R x C] -> out[Cpad x R] ----------------
__global__ void transpose_f16(const float* __restrict__ src,
                              __half* __restrict__ dst,
                              int R, int C, int Cpad) {
    __shared__ float tile[32][33];
    const int c0 = blockIdx.x * 32, r0 = blockIdx.y * 32;
    const int tx = threadIdx.x, ty = threadIdx.y;
    const int c = c0 + tx;
#pragma unroll
    for (int j = ty; j < 32; j += 8) {
        const int r = r0 + j;
        tile[j][tx] = (r < R && c < C) ? src[(size_t)r * C + c] : 0.f;
    }
    __syncthreads();
#pragma unroll
    for (int j = ty; j < 32; j += 8) {
        const int orow = c0 + j;
        const int ocol = r0 + tx;
        if (orow < Cpad && ocol < R)
            dst[(size_t)orow * R + ocol] = __float2half(tile[tx][j]);
    }
}

// ---------------- dt = softplus(raw + bias); dA = exp(dt * A) ----------------
__global__ void dt_kernel(const float* __restrict__ dt_bias,
                          const float* __restrict__ A_log) {
    int idx = blockIdx.x * blockDim.x + threadIdx.x;
    if (idx >= ROWS * NHEADS) return;
    int h = idx % NHEADS;
    int row = idx / NHEADS;
    float v = g_zxbcdt[(size_t)row * D_IN_PROJ + (D_INNER + CONV_DIM) + h] + dt_bias[h];
    float dtv = (v > 20.f) ? v : log1pf(expf(v));
    float A = -expf(A_log[h]);
    g_dt[idx] = dtv;
    g_dA[idx] = expf(dtv * A);
}

// ---------------- causal depthwise conv (width 4) + bias + silu ----------------
__global__ void conv_kernel(const float* __restrict__ conv_w,
                            const float* __restrict__ conv_b) {
    int idx = blockIdx.x * blockDim.x + threadIdx.x;
    if (idx >= ROWS * CONV_DIM) return;
    int c = idx % CONV_DIM;
    int row = idx / CONV_DIM;
    int l = row & (SEQLEN - 1);
    float acc = conv_b[c];
#pragma unroll
    for (int k = 0; k < D_CONV; k++) {
        int ls = l + k - (D_CONV - 1);
        if (ls >= 0)
            acc += g_zxbcdt[(size_t)(row + k - (D_CONV - 1)) * D_IN_PROJ + D_INNER + c] *
                   conv_w[c * D_CONV + k];
    }
    g_xBC[idx] = acc / (1.f + expf(-acc));
}

// ---------------- sequential SSM scan (HEADDIM split 4-ways) ----------------
#define PSPLIT 4
#define P_PER  (HEADDIM / PSPLIT)
__global__ void __launch_bounds__(256) scan_kernel(const float* __restrict__ Dparam) {
    __shared__ __align__(16) float sbuf[2][148];
    const int tid = threadIdx.x;
    const int blk = blockIdx.x;
    const int bh = blk / PSPLIT;
    const int ps = blk % PSPLIT;
    const int b = bh / NHEADS, h = bh % NHEADS;
    const int p0 = ps * P_PER;
    const int p_loc = tid >> 4;
    const int sub = tid & 15;
    const int n0 = sub * 4;

    float hreg[4] = {0.f, 0.f, 0.f, 0.f};
    const float Dh = Dparam[h];

    const float* xbase  = g_xBC + (size_t)b * SEQLEN * CONV_DIM;
    const float* dtbase = g_dt + (size_t)b * SEQLEN * NHEADS + h;
    const float* dAbase = g_dA + (size_t)b * SEQLEN * NHEADS + h;
    float*       ybase  = g_y + (size_t)b * SEQLEN * D_INNER + h * HEADDIM + p0;

    auto ld = [&](int t) -> float {
        const float* rowp = xbase + (size_t)t * CONV_DIM;
        if (tid < 16)   return rowp[h * HEADDIM + p0 + tid];
        if (tid < 80)   return rowp[D_INNER + (tid - 16)];
        if (tid < 144)  return rowp[D_INNER + D_STATE + (tid - 80)];
        if (tid == 144) return dtbase[(size_t)t * NHEADS];
        if (tid == 145) return dAbase[(size_t)t * NHEADS];
        return 0.f;
    };

    float q0 = ld(0), q1 = ld(1), q2 = ld(2), q3 = ld(3);
    if (tid < 146) sbuf[0][tid] = q0;
    q0 = q1; q1 = q2; q2 = q3;
    __syncthreads();

    for (int t = 0; t < SEQLEN; t++) {
        if (tid < 146) sbuf[(t + 1) & 1][tid] = q0;
        q0 = q1; q1 = q2;
        q2 = (t + 4 < SEQLEN) ? ld(t + 4) : 0.f;

        const float* sb = sbuf[t & 1];
        const float dt_t = sb[144];
        const float dA_t = sb[145];
        const float xv = sb[p_loc];
        const float coef = dt_t * xv;
        const float4 Bv = *(const float4*)&sb[16 + n0];
        const float4 Cv = *(const float4*)&sb[80 + n0];

        float acc;
        hreg[0] = hreg[0] * dA_t + coef * Bv.x; acc  = hreg[0] * Cv.x;
        hreg[1] = hreg[1] * dA_t + coef * Bv.y; acc += hreg[1] * Cv.y;
        hreg[2] = hreg[2] * dA_t + coef * Bv.z; acc += hreg[2] * Cv.z;
        hreg[3] = hreg[3] * dA_t + coef * Bv.w; acc += hreg[3] * Cv.w;

        acc += __shfl_xor_sync(0xffffffffu, acc, 1);
        acc += __shfl_xor_sync(0xffffffffu, acc, 2);
        acc += __shfl_xor_sync(0xffffffffu, acc, 4);
        acc += __shfl_xor_sync(0xffffffffu, acc, 8);
        if (sub == 0) ybase[(size_t)t * D_INNER + p_loc] = acc + Dh * xv;
        __syncthreads();
    }
}

// ---------------- gate + RMSNorm, writing fp16 hi/lo directly ----------------
__global__ void __launch_bounds__(256) norm_kernel(const float* __restrict__ norm_w) {
    const int row = blockIdx.x;
    const int tid = threadIdx.x;
    const float* zrow = g_zxbcdt + (size_t)row * D_IN_PROJ;
    const float* yrow = g_y + (size_t)row * D_INNER;
    __half* hrow = g_yhi + (size_t)row * D_INNER;
    __half* lrow = g_ylo + (size_t)row * D_INNER;

    float vals[6];
    float ss = 0.f;
#pragma unroll
    for (int i = 0; i < 6; i++) {
        int c = tid + i * 256;
        float z = zrow[c];
        float yv = yrow[c] * (z / (1.f + expf(-z)));
        vals[i] = yv;
        ss += yv * yv;
    }
#pragma unroll
    for (int o = 16; o; o >>= 1) ss += __shfl_xor_sync(0xffffffffu, ss, o);
    __shared__ float red[8];
    if ((tid & 31) == 0) red[tid >> 5] = ss;
    __syncthreads();
    if (tid < 8) {
        float v = red[tid];
#pragma unroll
        for (int o = 4; o; o >>= 1) v += __shfl_xor_sync(0xffu, v, o);
        if (tid == 0) red[0] = v;
    }
    __syncthreads();
    const float scale = rsqrtf(red[0] * (1.f / D_INNER) + 1e-5f);
#pragma unroll
    for (int i = 0; i < 6; i++) {
        int c = tid + i * 256;
        float yv = vals[i] * scale * norm_w[c];
        __half h = __float2half(yv);
        hrow[c] = h;
        lrow[c] = __float2half(yv - __half2float(h));
    }
}

// ---------------- launch ----------------
extern "C" void kernel_launch(void* const* d_in, const int* in_sizes, int n_in,
                              void* d_out, int out_size) {
    const float* x       = (const float*)d_in[0];
    const float* W_in    = (const float*)d_in[1];
    const float* conv_w  = (const float*)d_in[2];
    const float* conv_b  = (const float*)d_in[3];
    const float* dt_bias = (const float*)d_in[4];
    const float* A_log   = (const float*)d_in[5];
    const float* Dp      = (const float*)d_in[6];
    const float* norm_w  = (const float*)d_in[7];
    const float* W_out   = (const float*)d_in[8];
    float* out = (float*)d_out;

    float *zx_ptr;
    cudaGetSymbolAddress((void**)&zx_ptr, g_zxbcdt);
    __half *xhi, *xlo, *yhi, *ylo, *wi, *wo;
    cudaGetSymbolAddress((void**)&xhi, g_xhi);
    cudaGetSymbolAddress((void**)&xlo, g_xlo);
    cudaGetSymbolAddress((void**)&yhi, g_yhi);
    cudaGetSymbolAddress((void**)&ylo, g_ylo);
    cudaGetSymbolAddress((void**)&wi, g_wi);
    cudaGetSymbolAddress((void**)&wo, g_wo);

    static int smem_set = 0;
    if (!smem_set) {
        cudaFuncSetAttribute(mma_gemm, cudaFuncAttributeMaxDynamicSharedMemorySize, GSMEM);
        smem_set = 1;
    }

    // 1) split x -> fp16 hi/lo; transpose W_in -> fp16 [3328 x 768]
    convert_split<<<(ROWS * D_MODEL / 4 + 255) / 256, 256>>>(x, xhi, xlo, ROWS * D_MODEL / 4);
    transpose_f16<<<dim3(NPAD1 / 32, D_MODEL / 32), dim3(32, 8)>>>(
        W_in, wi, D_MODEL, D_IN_PROJ, NPAD1);

    // 2) zxbcdt = x @ W_in
    mma_gemm<<<dim3(NPAD1 / 128, ROWS / 128), 256, GSMEM>>>(
        xhi, xlo, wi, zx_ptr, ROWS, D_IN_PROJ, D_MODEL);

    // 3) dt / dA
    dt_kernel<<<(ROWS * NHEADS + 255) / 256, 256>>>(dt_bias, A_log);

    // 4) depthwise conv + silu
    conv_kernel<<<((size_t)ROWS * CONV_DIM + 255) / 256, 256>>>(conv_w, conv_b);

    // 5) sequential SSM scan
    scan_kernel<<<BATCH * NHEADS * PSPLIT, 256>>>(Dp);

    // 6) gate + RMSNorm (writes fp16 hi/lo directly)
    norm_kernel<<<ROWS, 256>>>(norm_w);

    // 7) transpose W_out -> fp16 [768 x 1536]
    transpose_f16<<<dim3(D_MODEL / 32, D_INNER / 32), dim3(32, 8)>>>(
        W_out, wo, D_INNER, D_MODEL, D_MODEL);

    // 8) out = y @ W_out
    mma_gemm<<<dim3(D_MODEL / 128, ROWS / 128), 256, GSMEM>>>(
        yhi, ylo, wo, out, ROWS, D_MODEL, D_INNER);
}

// round 6
// speedup vs baseline: 6.7710x; 2.7053x over previous
#include <cuda_runtime.h>
#include <cuda_fp16.h>
#include <math.h>
#include <stdint.h>

#define D_MODEL   768
#define D_STATE   64
#define D_CONV    4
#define HEADDIM   64
#define D_INNER   1536
#define NHEADS    24
#define CONV_DIM  1664
#define D_IN_PROJ 3224
#define BATCH     2
#define SEQLEN    4096
#define ROWS      (BATCH*SEQLEN)
#define NPAD1     3328
#define NCHUNK    64              // chunks per sequence
#define CT        64              // chunk length

// ---------------- scratch (device globals; no allocation) ----------------
__device__ float g_zxbcdt[(size_t)ROWS * D_IN_PROJ];
__device__ float g_xBC[(size_t)ROWS * CONV_DIM];
__device__ float g_y[(size_t)ROWS * D_INNER];
__device__ float g_dtT[(size_t)BATCH * NHEADS * SEQLEN];   // [bh][l]
__device__ float g_dtAT[(size_t)BATCH * NHEADS * SEQLEN];  // dt*A, [bh][l]
__device__ float g_S[(size_t)BATCH * NHEADS * NCHUNK * HEADDIM * D_STATE];
__device__ float g_H[(size_t)BATCH * NHEADS * NCHUNK * HEADDIM * D_STATE];
__device__ float g_P[(size_t)BATCH * NHEADS * NCHUNK];     // chunk log-decay
__device__ __half g_xhi[(size_t)ROWS * D_MODEL];
__device__ __half g_xlo[(size_t)ROWS * D_MODEL];
__device__ __half g_yhi[(size_t)ROWS * D_INNER];
__device__ __half g_ylo[(size_t)ROWS * D_INNER];
__device__ __half g_wi[(size_t)NPAD1 * D_MODEL];
__device__ __half g_wo[(size_t)D_MODEL * D_INNER];

// ---------------- warp-MMA fp16 GEMM (A split hi/lo, B single) ----------------
#define KC      32
#define PITCH   40
#define TILE_E  (128 * PITCH)
#define TILE_B  (TILE_E * 2)
#define STAGE_B (3 * TILE_B)
#define STAGES  3
#define GSMEM   (STAGES * STAGE_B)

__device__ __forceinline__ void cp16(uint32_t dst, const void* src) {
    asm volatile("cp.async.ca.shared.global [%0], [%1], 16;" :: "r"(dst), "l"(src) : "memory");
}
__device__ __forceinline__ void cp_commit() {
    asm volatile("cp.async.commit_group;" ::: "memory");
}
template <int N> __device__ __forceinline__ void cp_wait() {
    asm volatile("cp.async.wait_group %0;" :: "n"(N) : "memory");
}
__device__ __forceinline__ void ldsm4(uint32_t* r, uint32_t addr) {
    asm volatile("ldmatrix.sync.aligned.m8n8.x4.shared.b16 {%0,%1,%2,%3}, [%4];"
                 : "=r"(r[0]), "=r"(r[1]), "=r"(r[2]), "=r"(r[3]) : "r"(addr));
}
__device__ __forceinline__ void mma_f16(float* d, const uint32_t* a, uint32_t b0, uint32_t b1) {
    asm volatile("mma.sync.aligned.m16n8k16.row.col.f32.f16.f16.f32 "
                 "{%0,%1,%2,%3}, {%4,%5,%6,%7}, {%8,%9}, {%0,%1,%2,%3};"
                 : "+f"(d[0]), "+f"(d[1]), "+f"(d[2]), "+f"(d[3])
                 : "r"(a[0]), "r"(a[1]), "r"(a[2]), "r"(a[3]), "r"(b0), "r"(b1));
}

__global__ void __launch_bounds__(256, 2) mma_gemm(
    const __half* __restrict__ Ahi, const __half* __restrict__ Alo,
    const __half* __restrict__ Bh,
    float* __restrict__ C, int M, int N, int K) {
    extern __shared__ __half sm[];
    const int tid = threadIdx.x;
    const int wid = tid >> 5, lane = tid & 31;
    const int warp_m = wid >> 1, warp_n = wid & 1;
    const int g = lane >> 2, tig = lane & 3;
    const int bm = blockIdx.y * 128, bn = blockIdx.x * 128;
    const uint32_t sbase = (uint32_t)__cvta_generic_to_shared(sm);

    float acc[2][8][4];
#pragma unroll
    for (int mt = 0; mt < 2; mt++)
#pragma unroll
        for (int nt = 0; nt < 8; nt++)
#pragma unroll
            for (int i = 0; i < 4; i++) acc[mt][nt][i] = 0.f;

    const int nkt = K / KC;
    const int r_ld = tid >> 2, seg_ld = tid & 3;

    auto issue = [&](int kt) {
        const int st = kt % STAGES;
        const int kofs = kt * KC;
        const uint32_t dst0 = sbase + st * STAGE_B;
        const __half* srcs[3] = {Ahi, Alo, Bh};
#pragma unroll
        for (int arr = 0; arr < 3; arr++) {
            const int rbase = (arr < 2) ? bm : bn;
            const uint32_t db = dst0 + arr * TILE_B;
#pragma unroll
            for (int i = 0; i < 2; i++) {
                const int r = r_ld + i * 64;
                cp16(db + (uint32_t)(r * PITCH + seg_ld * 8) * 2,
                     srcs[arr] + (size_t)(rbase + r) * K + kofs + seg_ld * 8);
            }
        }
    };

    issue(0); cp_commit();
    if (nkt > 1) { issue(1); cp_commit(); }

    const int a_row = (lane & 15);
    const int a_col = (lane >> 4) * 8;
    const int b_row = (lane & 7) + ((lane >> 4) * 8);
    const int b_col = ((lane >> 3) & 1) * 8;

    for (int kt = 0; kt < nkt; kt++) {
        if (kt + 2 < nkt) cp_wait<1>(); else cp_wait<0>();
        __syncthreads();
        if (kt + 2 < nkt) { issue(kt + 2); cp_commit(); }

        const uint32_t st0 = sbase + (kt % STAGES) * STAGE_B;
        const uint32_t aHi = st0;
        const uint32_t aLo = st0 + TILE_B;
        const uint32_t bB  = st0 + 2 * TILE_B;

#pragma unroll
        for (int ks = 0; ks < KC; ks += 16) {
            uint32_t ah[2][4], al[2][4], bf[4][4];
#pragma unroll
            for (int mt = 0; mt < 2; mt++) {
                const uint32_t aoff =
                    (uint32_t)((warp_m * 32 + mt * 16 + a_row) * PITCH + ks + a_col) * 2;
                ldsm4(ah[mt], aHi + aoff);
                ldsm4(al[mt], aLo + aoff);
            }
#pragma unroll
            for (int ntp = 0; ntp < 4; ntp++) {
                const uint32_t boff =
                    (uint32_t)((warp_n * 64 + ntp * 16 + b_row) * PITCH + ks + b_col) * 2;
                ldsm4(bf[ntp], bB + boff);
            }
#pragma unroll
            for (int nt = 0; nt < 8; nt++) {
                const uint32_t b0 = bf[nt >> 1][(nt & 1) * 2];
                const uint32_t b1 = bf[nt >> 1][(nt & 1) * 2 + 1];
#pragma unroll
                for (int mt = 0; mt < 2; mt++) {
                    mma_f16(acc[mt][nt], ah[mt], b0, b1);
                    mma_f16(acc[mt][nt], al[mt], b0, b1);
                }
            }
        }
        __syncthreads();
    }

#pragma unroll
    for (int mt = 0; mt < 2; mt++) {
        const int row0 = bm + warp_m * 32 + mt * 16 + g;
#pragma unroll
        for (int nt = 0; nt < 8; nt++) {
            const int col = bn + warp_n * 64 + nt * 8 + 2 * tig;
            if (col < N) {
                *(float2*)&C[(size_t)row0 * N + col] = make_float2(acc[mt][nt][0], acc[mt][nt][1]);
                *(float2*)&C[(size_t)(row0 + 8) * N + col] = make_float2(acc[mt][nt][2], acc[mt][nt][3]);
            }
        }
    }
}

// ---------------- fp32 -> fp16 hi/lo split ----------------
__global__ void convert_split(const float* __restrict__ src,
                              __half* __restrict__ hi,
                              __half* __restrict__ lo, int n4) {
    int i = blockIdx.x * blockDim.x + threadIdx.x;
    if (i >= n4) return;
    const int idx = i * 4;
    float4 v = *(const float4*)(src + idx);
    __half h[4], l[4];
    h[0] = __float2half(v.x); l[0] = __float2half(v.x - __half2float(h[0]));
    h[1] = __float2half(v.y); l[1] = __float2half(v.y - __half2float(h[1]));
    h[2] = __float2half(v.z); l[2] = __float2half(v.z - __half2float(h[2]));
    h[3] = __float2half(v.w); l[3] = __float2half(v.w - __half2float(h[3]));
    *(uint2*)(hi + idx) = *(uint2*)h;
    *(uint2*)(lo + idx) = *(uint2*)l;
}

// ---------------- transpose to fp16: src[R x C] -> out[Cpad x R] ----------------
__global__ void transpose_f16(const float* __restrict__ src,
                              __half* __restrict__ dst,
                              int R, int C, int Cpad) {
    __shared__ float tile[32][33];
    const int c0 = blockIdx.x * 32, r0 = blockIdx.y * 32;
    const int tx = threadIdx.x, ty = threadIdx.y;
    const int c = c0 + tx;
#pragma unroll
    for (int j = ty; j < 32; j += 8) {
        const int r = r0 + j;
        tile[j][tx] = (r < R && c < C) ? src[(size_t)r * C + c] : 0.f;
    }
    __syncthreads();
#pragma unroll
    for (int j = ty; j < 32; j += 8) {
        const int orow = c0 + j;
        const int ocol = r0 + tx;
        if (orow < Cpad && ocol < R)
            dst[(size_t)orow * R + ocol] = __float2half(tile[tx][j]);
    }
}

// ---------------- dt: softplus; store dt and dt*A transposed [bh][l] ----------------
__global__ void dt_kernel(const float* __restrict__ dt_bias,
                          const float* __restrict__ A_log) {
    int idx = blockIdx.x * blockDim.x + threadIdx.x;
    if (idx >= BATCH * NHEADS * SEQLEN) return;
    const int l = idx % SEQLEN;
    const int bh = idx / SEQLEN;
    const int h = bh % NHEADS, b = bh / NHEADS;
    float v = g_zxbcdt[(size_t)(b * SEQLEN + l) * D_IN_PROJ + (D_INNER + CONV_DIM) + h]
              + dt_bias[h];
    float dtv = (v > 20.f) ? v : log1pf(expf(v));
    float A = -expf(A_log[h]);
    g_dtT[idx] = dtv;
    g_dtAT[idx] = dtv * A;
}

// ---------------- causal depthwise conv (width 4) + bias + silu ----------------
__global__ void conv_kernel(const float* __restrict__ conv_w,
                            const float* __restrict__ conv_b) {
    int idx = blockIdx.x * blockDim.x + threadIdx.x;
    if (idx >= ROWS * CONV_DIM) return;
    int c = idx % CONV_DIM;
    int row = idx / CONV_DIM;
    int l = row & (SEQLEN - 1);
    float acc = conv_b[c];
#pragma unroll
    for (int k = 0; k < D_CONV; k++) {
        int ls = l + k - (D_CONV - 1);
        if (ls >= 0)
            acc += g_zxbcdt[(size_t)(row + k - (D_CONV - 1)) * D_IN_PROJ + D_INNER + c] *
                   conv_w[c * D_CONV + k];
    }
    g_xBC[idx] = acc / (1.f + expf(-acc));
}

// ================= chunked SSM scan =================
#define PC 68   // smem pitch (floats)

// Phase A: S_c[p][n] = sum_t dt_t * exp(L63 - L_t) * x_t[p] * B_t[n]
__global__ void __launch_bounds__(256) chunk_state(void) {
    __shared__ float Xw[CT][PC];
    __shared__ float Bs[CT][PC];
    __shared__ float sL[CT], sdt[CT];
    const int c = blockIdx.x, h = blockIdx.y, b = blockIdx.z;
    const int tid = threadIdx.x;
    const int bh = b * NHEADS + h;
    const int rowbase = b * SEQLEN + c * CT;

    if (tid < CT) {
        sdt[tid] = g_dtT[(size_t)bh * SEQLEN + c * CT + tid];
        sL[tid]  = g_dtAT[(size_t)bh * SEQLEN + c * CT + tid];
    }
    __syncthreads();
    if (tid == 0) {
        float run = 0.f;
        for (int t = 0; t < CT; t++) { run += sL[t]; sL[t] = run; }
    }
    __syncthreads();
    const float Lend = sL[CT - 1];

    for (int e = tid; e < CT * 16; e += 256) {
        const int t = e >> 4, q = e & 15;
        const float* rowp = g_xBC + (size_t)(rowbase + t) * CONV_DIM;
        const float w = sdt[t] * expf(Lend - sL[t]);
        float4 xv = *(const float4*)(rowp + h * HEADDIM + q * 4);
        Xw[t][q * 4 + 0] = xv.x * w; Xw[t][q * 4 + 1] = xv.y * w;
        Xw[t][q * 4 + 2] = xv.z * w; Xw[t][q * 4 + 3] = xv.w * w;
        *(float4*)&Bs[t][q * 4] = *(const float4*)(rowp + D_INNER + q * 4);
    }
    __syncthreads();

    const int ti = tid >> 4, tj = tid & 15;
    float acc[4][4];
#pragma unroll
    for (int i = 0; i < 4; i++)
#pragma unroll
        for (int j = 0; j < 4; j++) acc[i][j] = 0.f;
    for (int k = 0; k < CT; k++) {
        float4 a4 = *(const float4*)&Xw[k][ti * 4];
        float4 b4 = *(const float4*)&Bs[k][tj * 4];
        const float a[4] = {a4.x, a4.y, a4.z, a4.w};
        const float bb[4] = {b4.x, b4.y, b4.z, b4.w};
#pragma unroll
        for (int i = 0; i < 4; i++)
#pragma unroll
            for (int j = 0; j < 4; j++) acc[i][j] += a[i] * bb[j];
    }
    float* Sbase = g_S + ((size_t)bh * NCHUNK + c) * (HEADDIM * D_STATE);
#pragma unroll
    for (int i = 0; i < 4; i++)
        *(float4*)&Sbase[(ti * 4 + i) * D_STATE + tj * 4] = *(float4*)acc[i];
    if (tid == 0) g_P[(size_t)bh * NCHUNK + c] = Lend;
}

// Phase B: h_init per chunk; h_{c+1} = exp(P_c) h_c + S_c
__global__ void __launch_bounds__(256) state_pass(void) {
    const int bh = blockIdx.x;
    const int tid = threadIdx.x;
    float hreg[16];
#pragma unroll
    for (int i = 0; i < 16; i++) hreg[i] = 0.f;
    for (int c = 0; c < NCHUNK; c++) {
        float* Hb = g_H + ((size_t)bh * NCHUNK + c) * (HEADDIM * D_STATE);
        const float* Sb = g_S + ((size_t)bh * NCHUNK + c) * (HEADDIM * D_STATE);
        const float P = expf(g_P[(size_t)bh * NCHUNK + c]);
#pragma unroll
        for (int i = 0; i < 16; i++) {
            Hb[tid + i * 256] = hreg[i];
            hreg[i] = P * hreg[i] + Sb[tid + i * 256];
        }
    }
}

// Phase C: Y = (mask∘(C·B^T)·decay) @ X + (C·h_init)·exp(L_t) + D·x
#define CSMEM (5 * CT * PC * 4 + 2 * CT * 4)
__global__ void __launch_bounds__(256) chunk_output(const float* __restrict__ Dparam) {
    extern __shared__ float cs[];
    float (*Ct)[PC] = (float(*)[PC])cs;                 // [n][t]
    float (*Bt)[PC] = (float(*)[PC])(cs + CT * PC);     // [n][s]
    float (*Xs)[PC] = (float(*)[PC])(cs + 2 * CT * PC); // [s][p]
    float (*Hn)[PC] = (float(*)[PC])(cs + 3 * CT * PC); // [n][p]
    float (*Gs)[PC] = (float(*)[PC])(cs + 4 * CT * PC); // [s][t]
    float* sL = cs + 5 * CT * PC;
    float* sdt = sL + CT;

    const int c = blockIdx.x, h = blockIdx.y, b = blockIdx.z;
    const int tid = threadIdx.x;
    const int bh = b * NHEADS + h;
    const int rowbase = b * SEQLEN + c * CT;
    const float Dh = Dparam[h];

    if (tid < CT) {
        sdt[tid] = g_dtT[(size_t)bh * SEQLEN + c * CT + tid];
        sL[tid]  = g_dtAT[(size_t)bh * SEQLEN + c * CT + tid];
    }
    __syncthreads();
    if (tid == 0) {
        float run = 0.f;
        for (int t = 0; t < CT; t++) { run += sL[t]; sL[t] = run; }
    }

    const float* Hbase = g_H + ((size_t)bh * NCHUNK + c) * (HEADDIM * D_STATE);
    for (int e = tid; e < CT * 16; e += 256) {
        const int t = e >> 4, q = e & 15;
        const float* rowp = g_xBC + (size_t)(rowbase + t) * CONV_DIM;
        float4 cv = *(const float4*)(rowp + D_INNER + D_STATE + q * 4);
        Ct[q * 4 + 0][t] = cv.x; Ct[q * 4 + 1][t] = cv.y;
        Ct[q * 4 + 2][t] = cv.z; Ct[q * 4 + 3][t] = cv.w;
        float4 bv = *(const float4*)(rowp + D_INNER + q * 4);
        Bt[q * 4 + 0][t] = bv.x; Bt[q * 4 + 1][t] = bv.y;
        Bt[q * 4 + 2][t] = bv.z; Bt[q * 4 + 3][t] = bv.w;
        *(float4*)&Xs[t][q * 4] = *(const float4*)(rowp + h * HEADDIM + q * 4);
        // Hn[n][p] from H[p][n]
        float4 hv = *(const float4*)(Hbase + t * D_STATE + q * 4);  // here t plays 'p'
        Hn[q * 4 + 0][t] = hv.x; Hn[q * 4 + 1][t] = hv.y;
        Hn[q * 4 + 2][t] = hv.z; Hn[q * 4 + 3][t] = hv.w;
    }
    __syncthreads();

    const int ti = tid >> 4, tj = tid & 15;
    // G[t][s] = sum_n Ct[n][t]*Bt[n][s]
    float acc[4][4];
#pragma unroll
    for (int i = 0; i < 4; i++)
#pragma unroll
        for (int j = 0; j < 4; j++) acc[i][j] = 0.f;
    for (int k = 0; k < CT; k++) {
        float4 a4 = *(const float4*)&Ct[k][ti * 4];
        float4 b4 = *(const float4*)&Bt[k][tj * 4];
        const float a[4] = {a4.x, a4.y, a4.z, a4.w};
        const float bb[4] = {b4.x, b4.y, b4.z, b4.w};
#pragma unroll
        for (int i = 0; i < 4; i++)
#pragma unroll
            for (int j = 0; j < 4; j++) acc[i][j] += a[i] * bb[j];
    }
    // weight + mask, write transposed Gs[s][t]
#pragma unroll
    for (int i = 0; i < 4; i++) {
        const int t = ti * 4 + i;
#pragma unroll
        for (int j = 0; j < 4; j++) {
            const int s = tj * 4 + j;
            float v = (s <= t) ? acc[i][j] * sdt[s] * expf(sL[t] - sL[s]) : 0.f;
            Gs[s][t] = v;
        }
    }
    __syncthreads();

    // Y1[t][p] = sum_s Gs[s][t]*Xs[s][p];  CH[t][p] = sum_n Ct[n][t]*Hn[n][p]
    float acc2[4][4];
#pragma unroll
    for (int i = 0; i < 4; i++)
#pragma unroll
        for (int j = 0; j < 4; j++) { acc[i][j] = 0.f; acc2[i][j] = 0.f; }
    for (int k = 0; k < CT; k++) {
        float4 a4 = *(const float4*)&Gs[k][ti * 4];
        float4 b4 = *(const float4*)&Xs[k][tj * 4];
        float4 c4 = *(const float4*)&Ct[k][ti * 4];
        float4 h4 = *(const float4*)&Hn[k][tj * 4];
        const float a[4] = {a4.x, a4.y, a4.z, a4.w};
        const float bb[4] = {b4.x, b4.y, b4.z, b4.w};
        const float cc[4] = {c4.x, c4.y, c4.z, c4.w};
        const float hh[4] = {h4.x, h4.y, h4.z, h4.w};
#pragma unroll
        for (int i = 0; i < 4; i++)
#pragma unroll
            for (int j = 0; j < 4; j++) {
                acc[i][j] += a[i] * bb[j];
                acc2[i][j] += cc[i] * hh[j];
            }
    }
#pragma unroll
    for (int i = 0; i < 4; i++) {
        const int t = ti * 4 + i;
        const float et = expf(sL[t]);
        float out4[4];
#pragma unroll
        for (int j = 0; j < 4; j++) {
            const int p = tj * 4 + j;
            out4[j] = acc[i][j] + acc2[i][j] * et + Dh * Xs[t][p];
        }
        *(float4*)&g_y[(size_t)(rowbase + t) * D_INNER + h * HEADDIM + tj * 4] =
            *(float4*)out4;
    }
}

// ---------------- gate + RMSNorm, writing fp16 hi/lo directly ----------------
__global__ void __launch_bounds__(256) norm_kernel(const float* __restrict__ norm_w) {
    const int row = blockIdx.x;
    const int tid = threadIdx.x;
    const float* zrow = g_zxbcdt + (size_t)row * D_IN_PROJ;
    const float* yrow = g_y + (size_t)row * D_INNER;
    __half* hrow = g_yhi + (size_t)row * D_INNER;
    __half* lrow = g_ylo + (size_t)row * D_INNER;

    float vals[6];
    float ss = 0.f;
#pragma unroll
    for (int i = 0; i < 6; i++) {
        int c = tid + i * 256;
        float z = zrow[c];
        float yv = yrow[c] * (z / (1.f + expf(-z)));
        vals[i] = yv;
        ss += yv * yv;
    }
#pragma unroll
    for (int o = 16; o; o >>= 1) ss += __shfl_xor_sync(0xffffffffu, ss, o);
    __shared__ float red[8];
    if ((tid & 31) == 0) red[tid >> 5] = ss;
    __syncthreads();
    if (tid < 8) {
        float v = red[tid];
#pragma unroll
        for (int o = 4; o; o >>= 1) v += __shfl_xor_sync(0xffu, v, o);
        if (tid == 0) red[0] = v;
    }
    __syncthreads();
    const float scale = rsqrtf(red[0] * (1.f / D_INNER) + 1e-5f);
#pragma unroll
    for (int i = 0; i < 6; i++) {
        int c = tid + i * 256;
        float yv = vals[i] * scale * norm_w[c];
        __half h = __float2half(yv);
        hrow[c] = h;
        lrow[c] = __float2half(yv - __half2float(h));
    }
}

// ---------------- launch ----------------
extern "C" void kernel_launch(void* const* d_in, const int* in_sizes, int n_in,
                              void* d_out, int out_size) {
    const float* x       = (const float*)d_in[0];
    const float* W_in    = (const float*)d_in[1];
    const float* conv_w  = (const float*)d_in[2];
    const float* conv_b  = (const float*)d_in[3];
    const float* dt_bias = (const float*)d_in[4];
    const float* A_log   = (const float*)d_in[5];
    const float* Dp      = (const float*)d_in[6];
    const float* norm_w  = (const float*)d_in[7];
    const float* W_out   = (const float*)d_in[8];
    float* out = (float*)d_out;

    float *zx_ptr;
    cudaGetSymbolAddress((void**)&zx_ptr, g_zxbcdt);
    __half *xhi, *xlo, *yhi, *ylo, *wi, *wo;
    cudaGetSymbolAddress((void**)&xhi, g_xhi);
    cudaGetSymbolAddress((void**)&xlo, g_xlo);
    cudaGetSymbolAddress((void**)&yhi, g_yhi);
    cudaGetSymbolAddress((void**)&ylo, g_ylo);
    cudaGetSymbolAddress((void**)&wi, g_wi);
    cudaGetSymbolAddress((void**)&wo, g_wo);

    static int attr_set = 0;
    if (!attr_set) {
        cudaFuncSetAttribute(mma_gemm, cudaFuncAttributeMaxDynamicSharedMemorySize, GSMEM);
        cudaFuncSetAttribute(chunk_output, cudaFuncAttributeMaxDynamicSharedMemorySize, CSMEM);
        attr_set = 1;
    }

    // 0-2) conversions (independent prep)
    convert_split<<<(ROWS * D_MODEL / 4 + 255) / 256, 256>>>(x, xhi, xlo, ROWS * D_MODEL / 4);
    transpose_f16<<<dim3(NPAD1 / 32, D_MODEL / 32), dim3(32, 8)>>>(
        W_in, wi, D_MODEL, D_IN_PROJ, NPAD1);
    transpose_f16<<<dim3(D_MODEL / 32, D_INNER / 32), dim3(32, 8)>>>(
        W_out, wo, D_INNER, D_MODEL, D_MODEL);

    // 3) zxbcdt = x @ W_in   (launch index 3 -> ncu profile slot)
    mma_gemm<<<dim3(NPAD1 / 128, ROWS / 128), 256, GSMEM>>>(
        xhi, xlo, wi, zx_ptr, ROWS, D_IN_PROJ, D_MODEL);

    // 4) dt / dtA (transposed layouts)
    dt_kernel<<<(BATCH * NHEADS * SEQLEN + 255) / 256, 256>>>(dt_bias, A_log);

    // 5) depthwise conv + silu
    conv_kernel<<<((size_t)ROWS * CONV_DIM + 255) / 256, 256>>>(conv_w, conv_b);

    // 6-8) chunked SSM scan
    chunk_state<<<dim3(NCHUNK, NHEADS, BATCH), 256>>>();
    state_pass<<<BATCH * NHEADS, 256>>>();
    chunk_output<<<dim3(NCHUNK, NHEADS, BATCH), 256, CSMEM>>>(Dp);

    // 9) gate + RMSNorm (writes fp16 hi/lo)
    norm_kernel<<<ROWS, 256>>>(norm_w);

    // 10) out = y @ W_out
    mma_gemm<<<dim3(D_MODEL / 128, ROWS / 128), 256, GSMEM>>>(
        yhi, ylo, wo, out, ROWS, D_MODEL, D_INNER);
}

// round 7
// speedup vs baseline: 7.2269x; 1.0673x over previous
#include <cuda_runtime.h>
#include <cuda_fp16.h>
#include <math.h>
#include <stdint.h>

#define D_MODEL   768
#define D_STATE   64
#define D_CONV    4
#define HEADDIM   64
#define D_INNER   1536
#define NHEADS    24
#define CONV_DIM  1664
#define D_IN_PROJ 3224
#define BATCH     2
#define SEQLEN    4096
#define ROWS      (BATCH*SEQLEN)
#define NPAD1     3328
#define NCHUNK    64
#define CT        64

// ---------------- scratch (device globals; no allocation) ----------------
__device__ float g_zxbcdt[(size_t)ROWS * D_IN_PROJ];
__device__ float g_xBC[(size_t)ROWS * CONV_DIM];
__device__ float g_y[(size_t)ROWS * D_INNER];
__device__ float g_dtT[(size_t)BATCH * NHEADS * SEQLEN];
__device__ float g_dtAT[(size_t)BATCH * NHEADS * SEQLEN];
__device__ float g_S[(size_t)BATCH * NHEADS * NCHUNK * HEADDIM * D_STATE];
__device__ float g_H[(size_t)BATCH * NHEADS * NCHUNK * HEADDIM * D_STATE];
__device__ float g_P[(size_t)BATCH * NHEADS * NCHUNK];
__device__ __half g_xhi[(size_t)ROWS * D_MODEL];
__device__ __half g_xlo[(size_t)ROWS * D_MODEL];
__device__ __half g_yhi[(size_t)ROWS * D_INNER];
__device__ __half g_ylo[(size_t)ROWS * D_INNER];
__device__ __half g_wi[(size_t)NPAD1 * D_MODEL];
__device__ __half g_wo[(size_t)D_MODEL * D_INNER];

// ---------------- common PTX helpers ----------------
__device__ __forceinline__ void cp16(uint32_t dst, const void* src) {
    asm volatile("cp.async.ca.shared.global [%0], [%1], 16;" :: "r"(dst), "l"(src) : "memory");
}
__device__ __forceinline__ void cp_commit() {
    asm volatile("cp.async.commit_group;" ::: "memory");
}
template <int N> __device__ __forceinline__ void cp_wait() {
    asm volatile("cp.async.wait_group %0;" :: "n"(N) : "memory");
}
__device__ __forceinline__ void ldsm4(uint32_t* r, uint32_t addr) {
    asm volatile("ldmatrix.sync.aligned.m8n8.x4.shared.b16 {%0,%1,%2,%3}, [%4];"
                 : "=r"(r[0]), "=r"(r[1]), "=r"(r[2]), "=r"(r[3]) : "r"(addr));
}
__device__ __forceinline__ void mma_f16(float* d, const uint32_t* a, uint32_t b0, uint32_t b1) {
    asm volatile("mma.sync.aligned.m16n8k16.row.col.f32.f16.f16.f32 "
                 "{%0,%1,%2,%3}, {%4,%5,%6,%7}, {%8,%9}, {%0,%1,%2,%3};"
                 : "+f"(d[0]), "+f"(d[1]), "+f"(d[2]), "+f"(d[3])
                 : "r"(a[0]), "r"(a[1]), "r"(a[2]), "r"(a[3]), "r"(b0), "r"(b1));
}

// ---------------- warp-MMA fp16 GEMM (unchanged from R6) ----------------
#define KC      32
#define PITCH   40
#define TILE_E  (128 * PITCH)
#define TILE_B  (TILE_E * 2)
#define STAGE_B (3 * TILE_B)
#define STAGES  3
#define GSMEM   (STAGES * STAGE_B)

__global__ void __launch_bounds__(256, 2) mma_gemm(
    const __half* __restrict__ Ahi, const __half* __restrict__ Alo,
    const __half* __restrict__ Bh,
    float* __restrict__ C, int M, int N, int K) {
    extern __shared__ __half sm[];
    const int tid = threadIdx.x;
    const int wid = tid >> 5, lane = tid & 31;
    const int warp_m = wid >> 1, warp_n = wid & 1;
    const int g = lane >> 2, tig = lane & 3;
    const int bm = blockIdx.y * 128, bn = blockIdx.x * 128;
    const uint32_t sbase = (uint32_t)__cvta_generic_to_shared(sm);

    float acc[2][8][4];
#pragma unroll
    for (int mt = 0; mt < 2; mt++)
#pragma unroll
        for (int nt = 0; nt < 8; nt++)
#pragma unroll
            for (int i = 0; i < 4; i++) acc[mt][nt][i] = 0.f;

    const int nkt = K / KC;
    const int r_ld = tid >> 2, seg_ld = tid & 3;

    auto issue = [&](int kt) {
        const int st = kt % STAGES;
        const int kofs = kt * KC;
        const uint32_t dst0 = sbase + st * STAGE_B;
        const __half* srcs[3] = {Ahi, Alo, Bh};
#pragma unroll
        for (int arr = 0; arr < 3; arr++) {
            const int rbase = (arr < 2) ? bm : bn;
            const uint32_t db = dst0 + arr * TILE_B;
#pragma unroll
            for (int i = 0; i < 2; i++) {
                const int r = r_ld + i * 64;
                cp16(db + (uint32_t)(r * PITCH + seg_ld * 8) * 2,
                     srcs[arr] + (size_t)(rbase + r) * K + kofs + seg_ld * 8);
            }
        }
    };

    issue(0); cp_commit();
    if (nkt > 1) { issue(1); cp_commit(); }

    const int a_row = (lane & 15);
    const int a_col = (lane >> 4) * 8;
    const int b_row = (lane & 7) + ((lane >> 4) * 8);
    const int b_col = ((lane >> 3) & 1) * 8;

    for (int kt = 0; kt < nkt; kt++) {
        if (kt + 2 < nkt) cp_wait<1>(); else cp_wait<0>();
        __syncthreads();
        if (kt + 2 < nkt) { issue(kt + 2); cp_commit(); }

        const uint32_t st0 = sbase + (kt % STAGES) * STAGE_B;
        const uint32_t aHi = st0;
        const uint32_t aLo = st0 + TILE_B;
        const uint32_t bB  = st0 + 2 * TILE_B;

#pragma unroll
        for (int ks = 0; ks < KC; ks += 16) {
            uint32_t ah[2][4], al[2][4], bf[4][4];
#pragma unroll
            for (int mt = 0; mt < 2; mt++) {
                const uint32_t aoff =
                    (uint32_t)((warp_m * 32 + mt * 16 + a_row) * PITCH + ks + a_col) * 2;
                ldsm4(ah[mt], aHi + aoff);
                ldsm4(al[mt], aLo + aoff);
            }
#pragma unroll
            for (int ntp = 0; ntp < 4; ntp++) {
                const uint32_t boff =
                    (uint32_t)((warp_n * 64 + ntp * 16 + b_row) * PITCH + ks + b_col) * 2;
                ldsm4(bf[ntp], bB + boff);
            }
#pragma unroll
            for (int nt = 0; nt < 8; nt++) {
                const uint32_t b0 = bf[nt >> 1][(nt & 1) * 2];
                const uint32_t b1 = bf[nt >> 1][(nt & 1) * 2 + 1];
#pragma unroll
                for (int mt = 0; mt < 2; mt++) {
                    mma_f16(acc[mt][nt], ah[mt], b0, b1);
                    mma_f16(acc[mt][nt], al[mt], b0, b1);
                }
            }
        }
        __syncthreads();
    }

#pragma unroll
    for (int mt = 0; mt < 2; mt++) {
        const int row0 = bm + warp_m * 32 + mt * 16 + g;
#pragma unroll
        for (int nt = 0; nt < 8; nt++) {
            const int col = bn + warp_n * 64 + nt * 8 + 2 * tig;
            if (col < N) {
                *(float2*)&C[(size_t)row0 * N + col] = make_float2(acc[mt][nt][0], acc[mt][nt][1]);
                *(float2*)&C[(size_t)(row0 + 8) * N + col] = make_float2(acc[mt][nt][2], acc[mt][nt][3]);
            }
        }
    }
}

// ---------------- fp32 -> fp16 hi/lo split ----------------
__global__ void convert_split(const float* __restrict__ src,
                              __half* __restrict__ hi,
                              __half* __restrict__ lo, int n4) {
    int i = blockIdx.x * blockDim.x + threadIdx.x;
    if (i >= n4) return;
    const int idx = i * 4;
    float4 v = *(const float4*)(src + idx);
    __half h[4], l[4];
    h[0] = __float2half(v.x); l[0] = __float2half(v.x - __half2float(h[0]));
    h[1] = __float2half(v.y); l[1] = __float2half(v.y - __half2float(h[1]));
    h[2] = __float2half(v.z); l[2] = __float2half(v.z - __half2float(h[2]));
    h[3] = __float2half(v.w); l[3] = __float2half(v.w - __half2float(h[3]));
    *(uint2*)(hi + idx) = *(uint2*)h;
    *(uint2*)(lo + idx) = *(uint2*)l;
}

// ---------------- transpose to fp16 ----------------
__global__ void transpose_f16(const float* __restrict__ src,
                              __half* __restrict__ dst,
                              int R, int C, int Cpad) {
    __shared__ float tile[32][33];
    const int c0 = blockIdx.x * 32, r0 = blockIdx.y * 32;
    const int tx = threadIdx.x, ty = threadIdx.y;
    const int c = c0 + tx;
#pragma unroll
    for (int j = ty; j < 32; j += 8) {
        const int r = r0 + j;
        tile[j][tx] = (r < R && c < C) ? src[(size_t)r * C + c] : 0.f;
    }
    __syncthreads();
#pragma unroll
    for (int j = ty; j < 32; j += 8) {
        const int orow = c0 + j;
        const int ocol = r0 + tx;
        if (orow < Cpad && ocol < R)
            dst[(size_t)orow * R + ocol] = __float2half(tile[tx][j]);
    }
}

// ---------------- dt ----------------
__global__ void dt_kernel(const float* __restrict__ dt_bias,
                          const float* __restrict__ A_log) {
    int idx = blockIdx.x * blockDim.x + threadIdx.x;
    if (idx >= BATCH * NHEADS * SEQLEN) return;
    const int l = idx % SEQLEN;
    const int bh = idx / SEQLEN;
    const int h = bh % NHEADS, b = bh / NHEADS;
    float v = g_zxbcdt[(size_t)(b * SEQLEN + l) * D_IN_PROJ + (D_INNER + CONV_DIM) + h]
              + dt_bias[h];
    float dtv = (v > 20.f) ? v : log1pf(expf(v));
    float A = -expf(A_log[h]);
    g_dtT[idx] = dtv;
    g_dtAT[idx] = dtv * A;
}

// ---------------- causal depthwise conv + silu ----------------
__global__ void conv_kernel(const float* __restrict__ conv_w,
                            const float* __restrict__ conv_b) {
    int idx = blockIdx.x * blockDim.x + threadIdx.x;
    if (idx >= ROWS * CONV_DIM) return;
    int c = idx % CONV_DIM;
    int row = idx / CONV_DIM;
    int l = row & (SEQLEN - 1);
    float acc = conv_b[c];
#pragma unroll
    for (int k = 0; k < D_CONV; k++) {
        int ls = l + k - (D_CONV - 1);
        if (ls >= 0)
            acc += g_zxbcdt[(size_t)(row + k - (D_CONV - 1)) * D_IN_PROJ + D_INNER + c] *
                   conv_w[c * D_CONV + k];
    }
    g_xBC[idx] = acc / (1.f + expf(-acc));
}

// ================= chunked SSM scan (tensor-core) =================
#define SPITCH 72   // halves per smem tile row; 144B rows (16B aligned)

// Phase A: S[p][n] = sum_t (dt_t*exp(Lend-L_t)*x_t[p]) * B_t[n]
__global__ void __launch_bounds__(256) chunk_state(void) {
    __shared__ __half sAh[CT * SPITCH], sAl[CT * SPITCH];
    __shared__ __half sBh[CT * SPITCH], sBl[CT * SPITCH];
    __shared__ float sL[CT], sdt[CT];
    const int c = blockIdx.x, h = blockIdx.y, b = blockIdx.z;
    const int tid = threadIdx.x;
    const int bh = b * NHEADS + h;
    const int rowbase = b * SEQLEN + c * CT;

    if (tid < CT) {
        sdt[tid] = g_dtT[(size_t)bh * SEQLEN + c * CT + tid];
        sL[tid]  = g_dtAT[(size_t)bh * SEQLEN + c * CT + tid];
    }
    __syncthreads();
    if (tid == 0) {
        float run = 0.f;
        for (int t = 0; t < CT; t++) { run += sL[t]; sL[t] = run; }
    }
    __syncthreads();
    const float Lend = sL[CT - 1];

    for (int e = tid; e < CT * 16; e += 256) {
        const int t = e >> 4, q = e & 15;
        const float* rowp = g_xBC + (size_t)(rowbase + t) * CONV_DIM;
        const float w = sdt[t] * expf(Lend - sL[t]);
        float4 xv = *(const float4*)(rowp + h * HEADDIM + q * 4);
        float4 bv = *(const float4*)(rowp + D_INNER + q * 4);
        const float xa[4] = {xv.x * w, xv.y * w, xv.z * w, xv.w * w};
        const float ba[4] = {bv.x, bv.y, bv.z, bv.w};
#pragma unroll
        for (int j = 0; j < 4; j++) {
            const int p = q * 4 + j;
            __half hx = __float2half(xa[j]);
            sAh[p * SPITCH + t] = hx;
            sAl[p * SPITCH + t] = __float2half(xa[j] - __half2float(hx));
            __half hb = __float2half(ba[j]);
            sBh[p * SPITCH + t] = hb;
            sBl[p * SPITCH + t] = __float2half(ba[j] - __half2float(hb));
        }
    }
    __syncthreads();

    const int wid = tid >> 5, lane = tid & 31;
    const int warp_m = wid & 3, warp_n = wid >> 2;
    const int a_row = lane & 15, a_col = (lane >> 4) * 8;
    const int b_row = (lane & 7) + ((lane >> 4) * 8), b_col = ((lane >> 3) & 1) * 8;
    const uint32_t uAh = (uint32_t)__cvta_generic_to_shared(sAh);
    const uint32_t uAl = (uint32_t)__cvta_generic_to_shared(sAl);
    const uint32_t uBh = (uint32_t)__cvta_generic_to_shared(sBh);
    const uint32_t uBl = (uint32_t)__cvta_generic_to_shared(sBl);

    float acc[4][4];
#pragma unroll
    for (int nt = 0; nt < 4; nt++)
#pragma unroll
        for (int i = 0; i < 4; i++) acc[nt][i] = 0.f;

#pragma unroll
    for (int kt = 0; kt < 4; kt++) {
        const int k0 = kt * 16;
        uint32_t ah[4], al[4], bh[2][4], bl[2][4];
        const uint32_t aoff = (uint32_t)((warp_m * 16 + a_row) * SPITCH + k0 + a_col) * 2;
        ldsm4(ah, uAh + aoff);
        ldsm4(al, uAl + aoff);
#pragma unroll
        for (int nb = 0; nb < 2; nb++) {
            const uint32_t boff =
                (uint32_t)((warp_n * 32 + nb * 16 + b_row) * SPITCH + k0 + b_col) * 2;
            ldsm4(bh[nb], uBh + boff);
            ldsm4(bl[nb], uBl + boff);
        }
#pragma unroll
        for (int nt = 0; nt < 4; nt++) {
            const int nb = nt >> 1, pr = (nt & 1) * 2;
            mma_f16(acc[nt], ah, bh[nb][pr], bh[nb][pr + 1]);
            mma_f16(acc[nt], ah, bl[nb][pr], bl[nb][pr + 1]);
            mma_f16(acc[nt], al, bh[nb][pr], bh[nb][pr + 1]);
        }
    }

    float* Sb = g_S + ((size_t)bh * NCHUNK + c) * (HEADDIM * D_STATE);
    const int g = lane >> 2, tig = lane & 3;
#pragma unroll
    for (int nt = 0; nt < 4; nt++) {
        const int ncol = warp_n * 32 + nt * 8 + 2 * tig;
        const int prow = warp_m * 16 + g;
        *(float2*)&Sb[prow * D_STATE + ncol] = make_float2(acc[nt][0], acc[nt][1]);
        *(float2*)&Sb[(prow + 8) * D_STATE + ncol] = make_float2(acc[nt][2], acc[nt][3]);
    }
    if (tid == 0) g_P[(size_t)bh * NCHUNK + c] = Lend;
}

// Phase B: h_init per chunk
__global__ void __launch_bounds__(256) state_pass(void) {
    const int bh = blockIdx.x;
    const int tid = threadIdx.x;
    float hreg[16];
#pragma unroll
    for (int i = 0; i < 16; i++) hreg[i] = 0.f;
    for (int c = 0; c < NCHUNK; c++) {
        float* Hb = g_H + ((size_t)bh * NCHUNK + c) * (HEADDIM * D_STATE);
        const float* Sb = g_S + ((size_t)bh * NCHUNK + c) * (HEADDIM * D_STATE);
        const float P = expf(g_P[(size_t)bh * NCHUNK + c]);
#pragma unroll
        for (int i = 0; i < 16; i++) {
            Hb[tid + i * 256] = hreg[i];
            hreg[i] = P * hreg[i] + Sb[tid + i * 256];
        }
    }
}

// Phase C (tensor-core): G=C.B^T -> mask/decay -> Y = G'.X + (C.h)*e^L + D*x
#define CTILE (CT * SPITCH)            // halves per tile
#define CSMEM (10 * CTILE * 2 + 2 * CT * 4)
__global__ void __launch_bounds__(256) chunk_output(const float* __restrict__ Dparam) {
    extern __shared__ __half cs[];
    __half* sCh = cs;                  // C [t][n]
    __half* sCl = cs + CTILE;
    __half* sB2h = cs + 2 * CTILE;     // B [s][n]
    __half* sB2l = cs + 3 * CTILE;
    __half* sXh = cs + 4 * CTILE;      // X^T [p][s]
    __half* sXl = cs + 5 * CTILE;
    __half* sHh = cs + 6 * CTILE;      // H [p][n]
    __half* sHl = cs + 7 * CTILE;
    __half* sGh = cs + 8 * CTILE;      // G' [t][s]
    __half* sGl = cs + 9 * CTILE;
    float* sL = (float*)(cs + 10 * CTILE);
    float* sdt = sL + CT;

    const int c = blockIdx.x, h = blockIdx.y, b = blockIdx.z;
    const int tid = threadIdx.x;
    const int bh = b * NHEADS + h;
    const int rowbase = b * SEQLEN + c * CT;
    const float Dh = Dparam[h];

    if (tid < CT) {
        sdt[tid] = g_dtT[(size_t)bh * SEQLEN + c * CT + tid];
        sL[tid]  = g_dtAT[(size_t)bh * SEQLEN + c * CT + tid];
    }
    __syncthreads();
    if (tid == 0) {
        float run = 0.f;
        for (int t = 0; t < CT; t++) { run += sL[t]; sL[t] = run; }
    }

    const float* Hbase = g_H + ((size_t)bh * NCHUNK + c) * (HEADDIM * D_STATE);
    for (int e = tid; e < CT * 16; e += 256) {
        const int t = e >> 4, q = e & 15;
        const float* rowp = g_xBC + (size_t)(rowbase + t) * CONV_DIM;
        float4 cv = *(const float4*)(rowp + D_INNER + D_STATE + q * 4);
        float4 bv = *(const float4*)(rowp + D_INNER + q * 4);
        float4 xv = *(const float4*)(rowp + h * HEADDIM + q * 4);
        float4 hv = *(const float4*)(Hbase + t * D_STATE + q * 4);   // t plays p
        const float ca[4] = {cv.x, cv.y, cv.z, cv.w};
        const float ba[4] = {bv.x, bv.y, bv.z, bv.w};
        const float xa[4] = {xv.x, xv.y, xv.z, xv.w};
        const float ha[4] = {hv.x, hv.y, hv.z, hv.w};
#pragma unroll
        for (int j = 0; j < 4; j++) {
            const int n = q * 4 + j;
            __half hc = __float2half(ca[j]);
            sCh[t * SPITCH + n] = hc;
            sCl[t * SPITCH + n] = __float2half(ca[j] - __half2float(hc));
            __half hb = __float2half(ba[j]);
            sB2h[t * SPITCH + n] = hb;
            sB2l[t * SPITCH + n] = __float2half(ba[j] - __half2float(hb));
            __half hx = __float2half(xa[j]);
            sXh[n * SPITCH + t] = hx;                     // transpose: [p][s]
            sXl[n * SPITCH + t] = __float2half(xa[j] - __half2float(hx));
            __half hh = __float2half(ha[j]);
            sHh[t * SPITCH + n] = hh;
            sHl[t * SPITCH + n] = __float2half(ha[j] - __half2float(hh));
        }
    }
    __syncthreads();

    const int wid = tid >> 5, lane = tid & 31;
    const int warp_m = wid & 3, warp_n = wid >> 2;
    const int a_row = lane & 15, a_col = (lane >> 4) * 8;
    const int b_row = (lane & 7) + ((lane >> 4) * 8), b_col = ((lane >> 3) & 1) * 8;
    const int g = lane >> 2, tig = lane & 3;
    const uint32_t uCh = (uint32_t)__cvta_generic_to_shared(sCh);
    const uint32_t uCl = (uint32_t)__cvta_generic_to_shared(sCl);
    const uint32_t uB2h = (uint32_t)__cvta_generic_to_shared(sB2h);
    const uint32_t uB2l = (uint32_t)__cvta_generic_to_shared(sB2l);
    const uint32_t uXh = (uint32_t)__cvta_generic_to_shared(sXh);
    const uint32_t uXl = (uint32_t)__cvta_generic_to_shared(sXl);
    const uint32_t uHh = (uint32_t)__cvta_generic_to_shared(sHh);
    const uint32_t uHl = (uint32_t)__cvta_generic_to_shared(sHl);
    const uint32_t uGh = (uint32_t)__cvta_generic_to_shared(sGh);
    const uint32_t uGl = (uint32_t)__cvta_generic_to_shared(sGl);

    // ---- Phase 1: G[t][s] = sum_n C[t][n]*B[s][n]
    float gacc[4][4];
#pragma unroll
    for (int nt = 0; nt < 4; nt++)
#pragma unroll
        for (int i = 0; i < 4; i++) gacc[nt][i] = 0.f;
#pragma unroll
    for (int kt = 0; kt < 4; kt++) {
        const int k0 = kt * 16;
        uint32_t ah[4], al[4], bh[2][4], bl[2][4];
        const uint32_t aoff = (uint32_t)((warp_m * 16 + a_row) * SPITCH + k0 + a_col) * 2;
        ldsm4(ah, uCh + aoff);
        ldsm4(al, uCl + aoff);
#pragma unroll
        for (int nb = 0; nb < 2; nb++) {
            const uint32_t boff =
                (uint32_t)((warp_n * 32 + nb * 16 + b_row) * SPITCH + k0 + b_col) * 2;
            ldsm4(bh[nb], uB2h + boff);
            ldsm4(bl[nb], uB2l + boff);
        }
#pragma unroll
        for (int nt = 0; nt < 4; nt++) {
            const int nb = nt >> 1, pr = (nt & 1) * 2;
            mma_f16(gacc[nt], ah, bh[nb][pr], bh[nb][pr + 1]);
            mma_f16(gacc[nt], ah, bl[nb][pr], bl[nb][pr + 1]);
            mma_f16(gacc[nt], al, bh[nb][pr], bh[nb][pr + 1]);
        }
    }
    __syncthreads();   // staged tiles consumed for phase-1 reads; G region free

    // ---- mask + decay, store G' (hi/lo) as [t][s]
#pragma unroll
    for (int nt = 0; nt < 4; nt++) {
        const int s0 = warp_n * 32 + nt * 8 + 2 * tig;
#pragma unroll
        for (int r = 0; r < 2; r++) {
            const int t = warp_m * 16 + g + r * 8;
            float v0 = gacc[nt][r * 2], v1 = gacc[nt][r * 2 + 1];
            const float Lt = sL[t];
            v0 = (s0 <= t)     ? v0 * sdt[s0]     * expf(Lt - sL[s0])     : 0.f;
            v1 = (s0 + 1 <= t) ? v1 * sdt[s0 + 1] * expf(Lt - sL[s0 + 1]) : 0.f;
            __half h0 = __float2half(v0), h1 = __float2half(v1);
            *(__half2*)&sGh[t * SPITCH + s0] = __halves2half2(h0, h1);
            *(__half2*)&sGl[t * SPITCH + s0] = __halves2half2(
                __float2half(v0 - __half2float(h0)), __float2half(v1 - __half2float(h1)));
        }
    }
    __syncthreads();

    // ---- Phase 2: Y1[t][p] = sum_s G'[t][s]*X^T[p][s];  CH[t][p] = sum_n C[t][n]*H[p][n]
    float yacc[4][4], cacc[4][4];
#pragma unroll
    for (int nt = 0; nt < 4; nt++)
#pragma unroll
        for (int i = 0; i < 4; i++) { yacc[nt][i] = 0.f; cacc[nt][i] = 0.f; }
#pragma unroll
    for (int kt = 0; kt < 4; kt++) {
        const int k0 = kt * 16;
        uint32_t gh[4], gl[4], ch[4], cl[4];
        uint32_t xh[2][4], xl[2][4], hh[2][4], hl[2][4];
        const uint32_t aoff = (uint32_t)((warp_m * 16 + a_row) * SPITCH + k0 + a_col) * 2;
        ldsm4(gh, uGh + aoff);
        ldsm4(gl, uGl + aoff);
        ldsm4(ch, uCh + aoff);
        ldsm4(cl, uCl + aoff);
#pragma unroll
        for (int nb = 0; nb < 2; nb++) {
            const uint32_t boff =
                (uint32_t)((warp_n * 32 + nb * 16 + b_row) * SPITCH + k0 + b_col) * 2;
            ldsm4(xh[nb], uXh + boff);
            ldsm4(xl[nb], uXl + boff);
            ldsm4(hh[nb], uHh + boff);
            ldsm4(hl[nb], uHl + boff);
        }
#pragma unroll
        for (int nt = 0; nt < 4; nt++) {
            const int nb = nt >> 1, pr = (nt & 1) * 2;
            mma_f16(yacc[nt], gh, xh[nb][pr], xh[nb][pr + 1]);
            mma_f16(yacc[nt], gh, xl[nb][pr], xl[nb][pr + 1]);
            mma_f16(yacc[nt], gl, xh[nb][pr], xh[nb][pr + 1]);
            mma_f16(cacc[nt], ch, hh[nb][pr], hh[nb][pr + 1]);
            mma_f16(cacc[nt], ch, hl[nb][pr], hl[nb][pr + 1]);
            mma_f16(cacc[nt], cl, hh[nb][pr], hh[nb][pr + 1]);
        }
    }

    // ---- epilogue: Y = Y1 + CH*exp(L_t) + D*x
#pragma unroll
    for (int nt = 0; nt < 4; nt++) {
        const int p = warp_n * 32 + nt * 8 + 2 * tig;
#pragma unroll
        for (int r = 0; r < 2; r++) {
            const int t = warp_m * 16 + g + r * 8;
            const float et = expf(sL[t]);
            const float x0 = __half2float(sXh[p * SPITCH + t]) + __half2float(sXl[p * SPITCH + t]);
            const float x1 = __half2float(sXh[(p + 1) * SPITCH + t]) + __half2float(sXl[(p + 1) * SPITCH + t]);
            const float o0 = yacc[nt][r * 2] + cacc[nt][r * 2] * et + Dh * x0;
            const float o1 = yacc[nt][r * 2 + 1] + cacc[nt][r * 2 + 1] * et + Dh * x1;
            *(float2*)&g_y[(size_t)(rowbase + t) * D_INNER + h * HEADDIM + p] =
                make_float2(o0, o1);
        }
    }
}

// ---------------- gate + RMSNorm, writing fp16 hi/lo ----------------
__global__ void __launch_bounds__(256) norm_kernel(const float* __restrict__ norm_w) {
    const int row = blockIdx.x;
    const int tid = threadIdx.x;
    const float* zrow = g_zxbcdt + (size_t)row * D_IN_PROJ;
    const float* yrow = g_y + (size_t)row * D_INNER;
    __half* hrow = g_yhi + (size_t)row * D_INNER;
    __half* lrow = g_ylo + (size_t)row * D_INNER;

    float vals[6];
    float ss = 0.f;
#pragma unroll
    for (int i = 0; i < 6; i++) {
        int c = tid + i * 256;
        float z = zrow[c];
        float yv = yrow[c] * (z / (1.f + expf(-z)));
        vals[i] = yv;
        ss += yv * yv;
    }
#pragma unroll
    for (int o = 16; o; o >>= 1) ss += __shfl_xor_sync(0xffffffffu, ss, o);
    __shared__ float red[8];
    if ((tid & 31) == 0) red[tid >> 5] = ss;
    __syncthreads();
    if (tid < 8) {
        float v = red[tid];
#pragma unroll
        for (int o = 4; o; o >>= 1) v += __shfl_xor_sync(0xffu, v, o);
        if (tid == 0) red[0] = v;
    }
    __syncthreads();
    const float scale = rsqrtf(red[0] * (1.f / D_INNER) + 1e-5f);
#pragma unroll
    for (int i = 0; i < 6; i++) {
        int c = tid + i * 256;
        float yv = vals[i] * scale * norm_w[c];
        __half h = __float2half(yv);
        hrow[c] = h;
        lrow[c] = __float2half(yv - __half2float(h));
    }
}

// ---------------- launch ----------------
extern "C" void kernel_launch(void* const* d_in, const int* in_sizes, int n_in,
                              void* d_out, int out_size) {
    const float* x       = (const float*)d_in[0];
    const float* W_in    = (const float*)d_in[1];
    const float* conv_w  = (const float*)d_in[2];
    const float* conv_b  = (const float*)d_in[3];
    const float* dt_bias = (const float*)d_in[4];
    const float* A_log   = (const float*)d_in[5];
    const float* Dp      = (const float*)d_in[6];
    const float* norm_w  = (const float*)d_in[7];
    const float* W_out   = (const float*)d_in[8];
    float* out = (float*)d_out;

    float *zx_ptr;
    cudaGetSymbolAddress((void**)&zx_ptr, g_zxbcdt);
    __half *xhi, *xlo, *yhi, *ylo, *wi, *wo;
    cudaGetSymbolAddress((void**)&xhi, g_xhi);
    cudaGetSymbolAddress((void**)&xlo, g_xlo);
    cudaGetSymbolAddress((void**)&yhi, g_yhi);
    cudaGetSymbolAddress((void**)&ylo, g_ylo);
    cudaGetSymbolAddress((void**)&wi, g_wi);
    cudaGetSymbolAddress((void**)&wo, g_wo);

    static int attr_set = 0;
    if (!attr_set) {
        cudaFuncSetAttribute(mma_gemm, cudaFuncAttributeMaxDynamicSharedMemorySize, GSMEM);
        cudaFuncSetAttribute(chunk_output, cudaFuncAttributeMaxDynamicSharedMemorySize, CSMEM);
        attr_set = 1;
    }

    // 0-2) conversions
    convert_split<<<(ROWS * D_MODEL / 4 + 255) / 256, 256>>>(x, xhi, xlo, ROWS * D_MODEL / 4);
    transpose_f16<<<dim3(NPAD1 / 32, D_MODEL / 32), dim3(32, 8)>>>(
        W_in, wi, D_MODEL, D_IN_PROJ, NPAD1);
    transpose_f16<<<dim3(D_MODEL / 32, D_INNER / 32), dim3(32, 8)>>>(
        W_out, wo, D_INNER, D_MODEL, D_MODEL);

    // 3) zxbcdt = x @ W_in   (launch index 3 -> ncu slot)
    mma_gemm<<<dim3(NPAD1 / 128, ROWS / 128), 256, GSMEM>>>(
        xhi, xlo, wi, zx_ptr, ROWS, D_IN_PROJ, D_MODEL);

    // 4) dt / dtA
    dt_kernel<<<(BATCH * NHEADS * SEQLEN + 255) / 256, 256>>>(dt_bias, A_log);

    // 5) conv + silu
    conv_kernel<<<((size_t)ROWS * CONV_DIM + 255) / 256, 256>>>(conv_w, conv_b);

    // 6-8) chunked SSM scan (tensor-core phases)
    chunk_state<<<dim3(NCHUNK, NHEADS, BATCH), 256>>>();
    state_pass<<<BATCH * NHEADS, 256>>>();
    chunk_output<<<dim3(NCHUNK, NHEADS, BATCH), 256, CSMEM>>>(Dp);

    // 9) gate + RMSNorm
    norm_kernel<<<ROWS, 256>>>(norm_w);

    // 10) out = y @ W_out
    mma_gemm<<<dim3(D_MODEL / 128, ROWS / 128), 256, GSMEM>>>(
        yhi, ylo, wo, out, ROWS, D_MODEL, D_INNER);
}

// round 8
// speedup vs baseline: 8.7523x; 1.2111x over previous
#include <cuda_runtime.h>
#include <cuda_fp16.h>
#include <math.h>
#include <stdint.h>

#define D_MODEL   768
#define D_STATE   64
#define D_CONV    4
#define HEADDIM   64
#define D_INNER   1536
#define NHEADS    24
#define CONV_DIM  1664
#define D_IN_PROJ 3224
#define BATCH     2
#define SEQLEN    4096
#define ROWS      (BATCH*SEQLEN)
#define NPAD1     3328
#define NCHUNK    64
#define CT        64

// ---------------- scratch (device globals; no allocation) ----------------
__device__ float g_zxbcdt[(size_t)ROWS * D_IN_PROJ];
__device__ float g_xBC[(size_t)ROWS * CONV_DIM];
__device__ float g_y[(size_t)ROWS * D_INNER];
__device__ float g_dtT[(size_t)BATCH * NHEADS * SEQLEN];
__device__ float g_dtAT[(size_t)BATCH * NHEADS * SEQLEN];
__device__ float g_S[(size_t)BATCH * NHEADS * NCHUNK * HEADDIM * D_STATE];
__device__ float g_H[(size_t)BATCH * NHEADS * NCHUNK * HEADDIM * D_STATE];
__device__ float g_P[(size_t)BATCH * NHEADS * NCHUNK];
__device__ __half g_xh[(size_t)ROWS * D_MODEL];
__device__ __half g_yh[(size_t)ROWS * D_INNER];
__device__ __half g_wi[(size_t)NPAD1 * D_MODEL];
__device__ __half g_wo[(size_t)D_MODEL * D_INNER];

// ---------------- common PTX helpers ----------------
__device__ __forceinline__ void cp16(uint32_t dst, const void* src) {
    asm volatile("cp.async.ca.shared.global [%0], [%1], 16;" :: "r"(dst), "l"(src) : "memory");
}
__device__ __forceinline__ void cp_commit() {
    asm volatile("cp.async.commit_group;" ::: "memory");
}
template <int N> __device__ __forceinline__ void cp_wait() {
    asm volatile("cp.async.wait_group %0;" :: "n"(N) : "memory");
}
__device__ __forceinline__ void ldsm4(uint32_t* r, uint32_t addr) {
    asm volatile("ldmatrix.sync.aligned.m8n8.x4.shared.b16 {%0,%1,%2,%3}, [%4];"
                 : "=r"(r[0]), "=r"(r[1]), "=r"(r[2]), "=r"(r[3]) : "r"(addr));
}
__device__ __forceinline__ void mma_f16(float* d, const uint32_t* a, uint32_t b0, uint32_t b1) {
    asm volatile("mma.sync.aligned.m16n8k16.row.col.f32.f16.f16.f32 "
                 "{%0,%1,%2,%3}, {%4,%5,%6,%7}, {%8,%9}, {%0,%1,%2,%3};"
                 : "+f"(d[0]), "+f"(d[1]), "+f"(d[2]), "+f"(d[3])
                 : "r"(a[0]), "r"(a[1]), "r"(a[2]), "r"(a[3]), "r"(b0), "r"(b1));
}

// ---------------- warp-MMA fp16 GEMM (single-precision operands) ----------------
#define KC      32
#define PITCH   40
#define TILE_E  (128 * PITCH)
#define TILE_B  (TILE_E * 2)
#define STAGE_B (2 * TILE_B)            // A, B tiles
#define STAGES  3
#define GSMEM   (STAGES * STAGE_B)      // 61440 bytes

__global__ void __launch_bounds__(256, 2) mma_gemm(
    const __half* __restrict__ Ah, const __half* __restrict__ Bh,
    float* __restrict__ C, int M, int N, int K) {
    extern __shared__ __half sm[];
    const int tid = threadIdx.x;
    const int wid = tid >> 5, lane = tid & 31;
    const int warp_m = wid >> 1, warp_n = wid & 1;
    const int g = lane >> 2, tig = lane & 3;
    const int bm = blockIdx.y * 128, bn = blockIdx.x * 128;
    const uint32_t sbase = (uint32_t)__cvta_generic_to_shared(sm);

    float acc[2][8][4];
#pragma unroll
    for (int mt = 0; mt < 2; mt++)
#pragma unroll
        for (int nt = 0; nt < 8; nt++)
#pragma unroll
            for (int i = 0; i < 4; i++) acc[mt][nt][i] = 0.f;

    const int nkt = K / KC;
    const int r_ld = tid >> 2, seg_ld = tid & 3;

    auto issue = [&](int kt) {
        const int st = kt % STAGES;
        const int kofs = kt * KC;
        const uint32_t dst0 = sbase + st * STAGE_B;
        const __half* srcs[2] = {Ah, Bh};
#pragma unroll
        for (int arr = 0; arr < 2; arr++) {
            const int rbase = (arr == 0) ? bm : bn;
            const uint32_t db = dst0 + arr * TILE_B;
#pragma unroll
            for (int i = 0; i < 2; i++) {
                const int r = r_ld + i * 64;
                cp16(db + (uint32_t)(r * PITCH + seg_ld * 8) * 2,
                     srcs[arr] + (size_t)(rbase + r) * K + kofs + seg_ld * 8);
            }
        }
    };

    issue(0); cp_commit();
    if (nkt > 1) { issue(1); cp_commit(); }

    const int a_row = (lane & 15);
    const int a_col = (lane >> 4) * 8;
    const int b_row = (lane & 7) + ((lane >> 4) * 8);
    const int b_col = ((lane >> 3) & 1) * 8;

    for (int kt = 0; kt < nkt; kt++) {
        if (kt + 2 < nkt) cp_wait<1>(); else cp_wait<0>();
        __syncthreads();
        if (kt + 2 < nkt) { issue(kt + 2); cp_commit(); }

        const uint32_t st0 = sbase + (kt % STAGES) * STAGE_B;
        const uint32_t aA = st0;
        const uint32_t bB = st0 + TILE_B;

#pragma unroll
        for (int ks = 0; ks < KC; ks += 16) {
            uint32_t ah[2][4], bf[4][4];
#pragma unroll
            for (int mt = 0; mt < 2; mt++) {
                const uint32_t aoff =
                    (uint32_t)((warp_m * 32 + mt * 16 + a_row) * PITCH + ks + a_col) * 2;
                ldsm4(ah[mt], aA + aoff);
            }
#pragma unroll
            for (int ntp = 0; ntp < 4; ntp++) {
                const uint32_t boff =
                    (uint32_t)((warp_n * 64 + ntp * 16 + b_row) * PITCH + ks + b_col) * 2;
                ldsm4(bf[ntp], bB + boff);
            }
#pragma unroll
            for (int nt = 0; nt < 8; nt++) {
                const uint32_t b0 = bf[nt >> 1][(nt & 1) * 2];
                const uint32_t b1 = bf[nt >> 1][(nt & 1) * 2 + 1];
#pragma unroll
                for (int mt = 0; mt < 2; mt++)
                    mma_f16(acc[mt][nt], ah[mt], b0, b1);
            }
        }
        __syncthreads();
    }

#pragma unroll
    for (int mt = 0; mt < 2; mt++) {
        const int row0 = bm + warp_m * 32 + mt * 16 + g;
#pragma unroll
        for (int nt = 0; nt < 8; nt++) {
            const int col = bn + warp_n * 64 + nt * 8 + 2 * tig;
            if (col < N) {
                *(float2*)&C[(size_t)row0 * N + col] = make_float2(acc[mt][nt][0], acc[mt][nt][1]);
                *(float2*)&C[(size_t)(row0 + 8) * N + col] = make_float2(acc[mt][nt][2], acc[mt][nt][3]);
            }
        }
    }
}

// ---------------- fp32 -> fp16 convert ----------------
__global__ void convert_f16(const float* __restrict__ src,
                            __half* __restrict__ dst, int n4) {
    int i = blockIdx.x * blockDim.x + threadIdx.x;
    if (i >= n4) return;
    const int idx = i * 4;
    float4 v = *(const float4*)(src + idx);
    __half h[4];
    h[0] = __float2half(v.x); h[1] = __float2half(v.y);
    h[2] = __float2half(v.z); h[3] = __float2half(v.w);
    *(uint2*)(dst + idx) = *(uint2*)h;
}

// ---------------- transpose to fp16 ----------------
__global__ void transpose_f16(const float* __restrict__ src,
                              __half* __restrict__ dst,
                              int R, int C, int Cpad) {
    __shared__ float tile[32][33];
    const int c0 = blockIdx.x * 32, r0 = blockIdx.y * 32;
    const int tx = threadIdx.x, ty = threadIdx.y;
    const int c = c0 + tx;
#pragma unroll
    for (int j = ty; j < 32; j += 8) {
        const int r = r0 + j;
        tile[j][tx] = (r < R && c < C) ? src[(size_t)r * C + c] : 0.f;
    }
    __syncthreads();
#pragma unroll
    for (int j = ty; j < 32; j += 8) {
        const int orow = c0 + j;
        const int ocol = r0 + tx;
        if (orow < Cpad && ocol < R)
            dst[(size_t)orow * R + ocol] = __float2half(tile[tx][j]);
    }
}

// ---------------- dt ----------------
__global__ void dt_kernel(const float* __restrict__ dt_bias,
                          const float* __restrict__ A_log) {
    int idx = blockIdx.x * blockDim.x + threadIdx.x;
    if (idx >= BATCH * NHEADS * SEQLEN) return;
    const int l = idx % SEQLEN;
    const int bh = idx / SEQLEN;
    const int h = bh % NHEADS, b = bh / NHEADS;
    float v = g_zxbcdt[(size_t)(b * SEQLEN + l) * D_IN_PROJ + (D_INNER + CONV_DIM) + h]
              + dt_bias[h];
    float dtv = (v > 20.f) ? v : log1pf(expf(v));
    float A = -expf(A_log[h]);
    g_dtT[idx] = dtv;
    g_dtAT[idx] = dtv * A;
}

// ---------------- causal depthwise conv + silu ----------------
__global__ void conv_kernel(const float* __restrict__ conv_w,
                            const float* __restrict__ conv_b) {
    int idx = blockIdx.x * blockDim.x + threadIdx.x;
    if (idx >= ROWS * CONV_DIM) return;
    int c = idx % CONV_DIM;
    int row = idx / CONV_DIM;
    int l = row & (SEQLEN - 1);
    float acc = conv_b[c];
#pragma unroll
    for (int k = 0; k < D_CONV; k++) {
        int ls = l + k - (D_CONV - 1);
        if (ls >= 0)
            acc += g_zxbcdt[(size_t)(row + k - (D_CONV - 1)) * D_IN_PROJ + D_INNER + c] *
                   conv_w[c * D_CONV + k];
    }
    g_xBC[idx] = acc / (1.f + expf(-acc));
}

// ================= chunked SSM scan (tensor-core) =================
#define SPITCH 72

// Phase A: S[p][n] = sum_t (dt_t*exp(Lend-L_t)*x_t[p]) * B_t[n]
__global__ void __launch_bounds__(256) chunk_state(void) {
    __shared__ __half sAh[CT * SPITCH], sAl[CT * SPITCH];
    __shared__ __half sBh[CT * SPITCH], sBl[CT * SPITCH];
    __shared__ float sL[CT], sdt[CT];
    const int c = blockIdx.x, h = blockIdx.y, b = blockIdx.z;
    const int tid = threadIdx.x;
    const int bh = b * NHEADS + h;
    const int rowbase = b * SEQLEN + c * CT;

    if (tid < CT) {
        sdt[tid] = g_dtT[(size_t)bh * SEQLEN + c * CT + tid];
        sL[tid]  = g_dtAT[(size_t)bh * SEQLEN + c * CT + tid];
    }
    __syncthreads();
    if (tid == 0) {
        float run = 0.f;
        for (int t = 0; t < CT; t++) { run += sL[t]; sL[t] = run; }
    }
    __syncthreads();
    const float Lend = sL[CT - 1];

    for (int e = tid; e < CT * 16; e += 256) {
        const int t = e >> 4, q = e & 15;
        const float* rowp = g_xBC + (size_t)(rowbase + t) * CONV_DIM;
        const float w = sdt[t] * expf(Lend - sL[t]);
        float4 xv = *(const float4*)(rowp + h * HEADDIM + q * 4);
        float4 bv = *(const float4*)(rowp + D_INNER + q * 4);
        const float xa[4] = {xv.x * w, xv.y * w, xv.z * w, xv.w * w};
        const float ba[4] = {bv.x, bv.y, bv.z, bv.w};
#pragma unroll
        for (int j = 0; j < 4; j++) {
            const int p = q * 4 + j;
            __half hx = __float2half(xa[j]);
            sAh[p * SPITCH + t] = hx;
            sAl[p * SPITCH + t] = __float2half(xa[j] - __half2float(hx));
            __half hb = __float2half(ba[j]);
            sBh[p * SPITCH + t] = hb;
            sBl[p * SPITCH + t] = __float2half(ba[j] - __half2float(hb));
        }
    }
    __syncthreads();

    const int wid = tid >> 5, lane = tid & 31;
    const int warp_m = wid & 3, warp_n = wid >> 2;
    const int a_row = lane & 15, a_col = (lane >> 4) * 8;
    const int b_row = (lane & 7) + ((lane >> 4) * 8), b_col = ((lane >> 3) & 1) * 8;
    const uint32_t uAh = (uint32_t)__cvta_generic_to_shared(sAh);
    const uint32_t uAl = (uint32_t)__cvta_generic_to_shared(sAl);
    const uint32_t uBh = (uint32_t)__cvta_generic_to_shared(sBh);
    const uint32_t uBl = (uint32_t)__cvta_generic_to_shared(sBl);

    float acc[4][4];
#pragma unroll
    for (int nt = 0; nt < 4; nt++)
#pragma unroll
        for (int i = 0; i < 4; i++) acc[nt][i] = 0.f;

#pragma unroll
    for (int kt = 0; kt < 4; kt++) {
        const int k0 = kt * 16;
        uint32_t ah[4], al[4], bh[2][4], bl[2][4];
        const uint32_t aoff = (uint32_t)((warp_m * 16 + a_row) * SPITCH + k0 + a_col) * 2;
        ldsm4(ah, uAh + aoff);
        ldsm4(al, uAl + aoff);
#pragma unroll
        for (int nb = 0; nb < 2; nb++) {
            const uint32_t boff =
                (uint32_t)((warp_n * 32 + nb * 16 + b_row) * SPITCH + k0 + b_col) * 2;
            ldsm4(bh[nb], uBh + boff);
            ldsm4(bl[nb], uBl + boff);
        }
#pragma unroll
        for (int nt = 0; nt < 4; nt++) {
            const int nb = nt >> 1, pr = (nt & 1) * 2;
            mma_f16(acc[nt], ah, bh[nb][pr], bh[nb][pr + 1]);
            mma_f16(acc[nt], ah, bl[nb][pr], bl[nb][pr + 1]);
            mma_f16(acc[nt], al, bh[nb][pr], bh[nb][pr + 1]);
        }
    }

    float* Sb = g_S + ((size_t)bh * NCHUNK + c) * (HEADDIM * D_STATE);
    const int g = lane >> 2, tig = lane & 3;
#pragma unroll
    for (int nt = 0; nt < 4; nt++) {
        const int ncol = warp_n * 32 + nt * 8 + 2 * tig;
        const int prow = warp_m * 16 + g;
        *(float2*)&Sb[prow * D_STATE + ncol] = make_float2(acc[nt][0], acc[nt][1]);
        *(float2*)&Sb[(prow + 8) * D_STATE + ncol] = make_float2(acc[nt][2], acc[nt][3]);
    }
    if (tid == 0) g_P[(size_t)bh * NCHUNK + c] = Lend;
}

// Phase B: h_init per chunk
__global__ void __launch_bounds__(256) state_pass(void) {
    const int bh = blockIdx.x;
    const int tid = threadIdx.x;
    float hreg[16];
#pragma unroll
    for (int i = 0; i < 16; i++) hreg[i] = 0.f;
    for (int c = 0; c < NCHUNK; c++) {
        float* Hb = g_H + ((size_t)bh * NCHUNK + c) * (HEADDIM * D_STATE);
        const float* Sb = g_S + ((size_t)bh * NCHUNK + c) * (HEADDIM * D_STATE);
        const float P = expf(g_P[(size_t)bh * NCHUNK + c]);
#pragma unroll
        for (int i = 0; i < 16; i++) {
            Hb[tid + i * 256] = hreg[i];
            hreg[i] = P * hreg[i] + Sb[tid + i * 256];
        }
    }
}

// Phase C (tensor-core)
#define CTILE (CT * SPITCH)
#define CSMEM (10 * CTILE * 2 + 2 * CT * 4)
__global__ void __launch_bounds__(256) chunk_output(const float* __restrict__ Dparam) {
    extern __shared__ __half cs[];
    __half* sCh = cs;
    __half* sCl = cs + CTILE;
    __half* sB2h = cs + 2 * CTILE;
    __half* sB2l = cs + 3 * CTILE;
    __half* sXh = cs + 4 * CTILE;
    __half* sXl = cs + 5 * CTILE;
    __half* sHh = cs + 6 * CTILE;
    __half* sHl = cs + 7 * CTILE;
    __half* sGh = cs + 8 * CTILE;
    __half* sGl = cs + 9 * CTILE;
    float* sL = (float*)(cs + 10 * CTILE);
    float* sdt = sL + CT;

    const int c = blockIdx.x, h = blockIdx.y, b = blockIdx.z;
    const int tid = threadIdx.x;
    const int bh = b * NHEADS + h;
    const int rowbase = b * SEQLEN + c * CT;
    const float Dh = Dparam[h];

    if (tid < CT) {
        sdt[tid] = g_dtT[(size_t)bh * SEQLEN + c * CT + tid];
        sL[tid]  = g_dtAT[(size_t)bh * SEQLEN + c * CT + tid];
    }
    __syncthreads();
    if (tid == 0) {
        float run = 0.f;
        for (int t = 0; t < CT; t++) { run += sL[t]; sL[t] = run; }
    }

    const float* Hbase = g_H + ((size_t)bh * NCHUNK + c) * (HEADDIM * D_STATE);
    for (int e = tid; e < CT * 16; e += 256) {
        const int t = e >> 4, q = e & 15;
        const float* rowp = g_xBC + (size_t)(rowbase + t) * CONV_DIM;
        float4 cv = *(const float4*)(rowp + D_INNER + D_STATE + q * 4);
        float4 bv = *(const float4*)(rowp + D_INNER + q * 4);
        float4 xv = *(const float4*)(rowp + h * HEADDIM + q * 4);
        float4 hv = *(const float4*)(Hbase + t * D_STATE + q * 4);
        const float ca[4] = {cv.x, cv.y, cv.z, cv.w};
        const float ba[4] = {bv.x, bv.y, bv.z, bv.w};
        const float xa[4] = {xv.x, xv.y, xv.z, xv.w};
        const float ha[4] = {hv.x, hv.y, hv.z, hv.w};
#pragma unroll
        for (int j = 0; j < 4; j++) {
            const int n = q * 4 + j;
            __half hc = __float2half(ca[j]);
            sCh[t * SPITCH + n] = hc;
            sCl[t * SPITCH + n] = __float2half(ca[j] - __half2float(hc));
            __half hb = __float2half(ba[j]);
            sB2h[t * SPITCH + n] = hb;
            sB2l[t * SPITCH + n] = __float2half(ba[j] - __half2float(hb));
            __half hx = __float2half(xa[j]);
            sXh[n * SPITCH + t] = hx;
            sXl[n * SPITCH + t] = __float2half(xa[j] - __half2float(hx));
            __half hh = __float2half(ha[j]);
            sHh[t * SPITCH + n] = hh;
            sHl[t * SPITCH + n] = __float2half(ha[j] - __half2float(hh));
        }
    }
    __syncthreads();

    const int wid = tid >> 5, lane = tid & 31;
    const int warp_m = wid & 3, warp_n = wid >> 2;
    const int a_row = lane & 15, a_col = (lane >> 4) * 8;
    const int b_row = (lane & 7) + ((lane >> 4) * 8), b_col = ((lane >> 3) & 1) * 8;
    const int g = lane >> 2, tig = lane & 3;
    const uint32_t uCh = (uint32_t)__cvta_generic_to_shared(sCh);
    const uint32_t uCl = (uint32_t)__cvta_generic_to_shared(sCl);
    const uint32_t uB2h = (uint32_t)__cvta_generic_to_shared(sB2h);
    const uint32_t uB2l = (uint32_t)__cvta_generic_to_shared(sB2l);
    const uint32_t uXh = (uint32_t)__cvta_generic_to_shared(sXh);
    const uint32_t uXl = (uint32_t)__cvta_generic_to_shared(sXl);
    const uint32_t uHh = (uint32_t)__cvta_generic_to_shared(sHh);
    const uint32_t uHl = (uint32_t)__cvta_generic_to_shared(sHl);
    const uint32_t uGh = (uint32_t)__cvta_generic_to_shared(sGh);
    const uint32_t uGl = (uint32_t)__cvta_generic_to_shared(sGl);

    float gacc[4][4];
#pragma unroll
    for (int nt = 0; nt < 4; nt++)
#pragma unroll
        for (int i = 0; i < 4; i++) gacc[nt][i] = 0.f;
#pragma unroll
    for (int kt = 0; kt < 4; kt++) {
        const int k0 = kt * 16;
        uint32_t ah[4], al[4], bh[2][4], bl[2][4];
        const uint32_t aoff = (uint32_t)((warp_m * 16 + a_row) * SPITCH + k0 + a_col) * 2;
        ldsm4(ah, uCh + aoff);
        ldsm4(al, uCl + aoff);
#pragma unroll
        for (int nb = 0; nb < 2; nb++) {
            const uint32_t boff =
                (uint32_t)((warp_n * 32 + nb * 16 + b_row) * SPITCH + k0 + b_col) * 2;
            ldsm4(bh[nb], uB2h + boff);
            ldsm4(bl[nb], uB2l + boff);
        }
#pragma unroll
        for (int nt = 0; nt < 4; nt++) {
            const int nb = nt >> 1, pr = (nt & 1) * 2;
            mma_f16(gacc[nt], ah, bh[nb][pr], bh[nb][pr + 1]);
            mma_f16(gacc[nt], ah, bl[nb][pr], bl[nb][pr + 1]);
            mma_f16(gacc[nt], al, bh[nb][pr], bh[nb][pr + 1]);
        }
    }
    __syncthreads();

#pragma unroll
    for (int nt = 0; nt < 4; nt++) {
        const int s0 = warp_n * 32 + nt * 8 + 2 * tig;
#pragma unroll
        for (int r = 0; r < 2; r++) {
            const int t = warp_m * 16 + g + r * 8;
            float v0 = gacc[nt][r * 2], v1 = gacc[nt][r * 2 + 1];
            const float Lt = sL[t];
            v0 = (s0 <= t)     ? v0 * sdt[s0]     * expf(Lt - sL[s0])     : 0.f;
            v1 = (s0 + 1 <= t) ? v1 * sdt[s0 + 1] * expf(Lt - sL[s0 + 1]) : 0.f;
            __half h0 = __float2half(v0), h1 = __float2half(v1);
            *(__half2*)&sGh[t * SPITCH + s0] = __halves2half2(h0, h1);
            *(__half2*)&sGl[t * SPITCH + s0] = __halves2half2(
                __float2half(v0 - __half2float(h0)), __float2half(v1 - __half2float(h1)));
        }
    }
    __syncthreads();

    float yacc[4][4], cacc[4][4];
#pragma unroll
    for (int nt = 0; nt < 4; nt++)
#pragma unroll
        for (int i = 0; i < 4; i++) { yacc[nt][i] = 0.f; cacc[nt][i] = 0.f; }
#pragma unroll
    for (int kt = 0; kt < 4; kt++) {
        const int k0 = kt * 16;
        uint32_t gh[4], gl[4], ch[4], cl[4];
        uint32_t xh[2][4], xl[2][4], hh[2][4], hl[2][4];
        const uint32_t aoff = (uint32_t)((warp_m * 16 + a_row) * SPITCH + k0 + a_col) * 2;
        ldsm4(gh, uGh + aoff);
        ldsm4(gl, uGl + aoff);
        ldsm4(ch, uCh + aoff);
        ldsm4(cl, uCl + aoff);
#pragma unroll
        for (int nb = 0; nb < 2; nb++) {
            const uint32_t boff =
                (uint32_t)((warp_n * 32 + nb * 16 + b_row) * SPITCH + k0 + b_col) * 2;
            ldsm4(xh[nb], uXh + boff);
            ldsm4(xl[nb], uXl + boff);
            ldsm4(hh[nb], uHh + boff);
            ldsm4(hl[nb], uHl + boff);
        }
#pragma unroll
        for (int nt = 0; nt < 4; nt++) {
            const int nb = nt >> 1, pr = (nt & 1) * 2;
            mma_f16(yacc[nt], gh, xh[nb][pr], xh[nb][pr + 1]);
            mma_f16(yacc[nt], gh, xl[nb][pr], xl[nb][pr + 1]);
            mma_f16(yacc[nt], gl, xh[nb][pr], xh[nb][pr + 1]);
            mma_f16(cacc[nt], ch, hh[nb][pr], hh[nb][pr + 1]);
            mma_f16(cacc[nt], ch, hl[nb][pr], hl[nb][pr + 1]);
            mma_f16(cacc[nt], cl, hh[nb][pr], hh[nb][pr + 1]);
        }
    }

#pragma unroll
    for (int nt = 0; nt < 4; nt++) {
        const int p = warp_n * 32 + nt * 8 + 2 * tig;
#pragma unroll
        for (int r = 0; r < 2; r++) {
            const int t = warp_m * 16 + g + r * 8;
            const float et = expf(sL[t]);
            const float x0 = __half2float(sXh[p * SPITCH + t]) + __half2float(sXl[p * SPITCH + t]);
            const float x1 = __half2float(sXh[(p + 1) * SPITCH + t]) + __half2float(sXl[(p + 1) * SPITCH + t]);
            const float o0 = yacc[nt][r * 2] + cacc[nt][r * 2] * et + Dh * x0;
            const float o1 = yacc[nt][r * 2 + 1] + cacc[nt][r * 2 + 1] * et + Dh * x1;
            *(float2*)&g_y[(size_t)(rowbase + t) * D_INNER + h * HEADDIM + p] =
                make_float2(o0, o1);
        }
    }
}

// ---------------- gate + RMSNorm, writing fp16 ----------------
__global__ void __launch_bounds__(256) norm_kernel(const float* __restrict__ norm_w) {
    const int row = blockIdx.x;
    const int tid = threadIdx.x;
    const float* zrow = g_zxbcdt + (size_t)row * D_IN_PROJ;
    const float* yrow = g_y + (size_t)row * D_INNER;
    __half* hrow = g_yh + (size_t)row * D_INNER;

    float vals[6];
    float ss = 0.f;
#pragma unroll
    for (int i = 0; i < 6; i++) {
        int c = tid + i * 256;
        float z = zrow[c];
        float yv = yrow[c] * (z / (1.f + expf(-z)));
        vals[i] = yv;
        ss += yv * yv;
    }
#pragma unroll
    for (int o = 16; o; o >>= 1) ss += __shfl_xor_sync(0xffffffffu, ss, o);
    __shared__ float red[8];
    if ((tid & 31) == 0) red[tid >> 5] = ss;
    __syncthreads();
    if (tid < 8) {
        float v = red[tid];
#pragma unroll
        for (int o = 4; o; o >>= 1) v += __shfl_xor_sync(0xffu, v, o);
        if (tid == 0) red[0] = v;
    }
    __syncthreads();
    const float scale = rsqrtf(red[0] * (1.f / D_INNER) + 1e-5f);
#pragma unroll
    for (int i = 0; i < 6; i++) {
        int c = tid + i * 256;
        hrow[c] = __float2half(vals[i] * scale * norm_w[c]);
    }
}

// ---------------- launch ----------------
extern "C" void kernel_launch(void* const* d_in, const int* in_sizes, int n_in,
                              void* d_out, int out_size) {
    const float* x       = (const float*)d_in[0];
    const float* W_in    = (const float*)d_in[1];
    const float* conv_w  = (const float*)d_in[2];
    const float* conv_b  = (const float*)d_in[3];
    const float* dt_bias = (const float*)d_in[4];
    const float* A_log   = (const float*)d_in[5];
    const float* Dp      = (const float*)d_in[6];
    const float* norm_w  = (const float*)d_in[7];
    const float* W_out   = (const float*)d_in[8];
    float* out = (float*)d_out;

    float *zx_ptr;
    cudaGetSymbolAddress((void**)&zx_ptr, g_zxbcdt);
    __half *xh, *yh, *wi, *wo;
    cudaGetSymbolAddress((void**)&xh, g_xh);
    cudaGetSymbolAddress((void**)&yh, g_yh);
    cudaGetSymbolAddress((void**)&wi, g_wi);
    cudaGetSymbolAddress((void**)&wo, g_wo);

    static int attr_set = 0;
    if (!attr_set) {
        cudaFuncSetAttribute(mma_gemm, cudaFuncAttributeMaxDynamicSharedMemorySize, GSMEM);
        cudaFuncSetAttribute(chunk_output, cudaFuncAttributeMaxDynamicSharedMemorySize, CSMEM);
        attr_set = 1;
    }

    // 0-2) conversions
    convert_f16<<<(ROWS * D_MODEL / 4 + 255) / 256, 256>>>(x, xh, ROWS * D_MODEL / 4);
    transpose_f16<<<dim3(NPAD1 / 32, D_MODEL / 32), dim3(32, 8)>>>(
        W_in, wi, D_MODEL, D_IN_PROJ, NPAD1);
    transpose_f16<<<dim3(D_MODEL / 32, D_INNER / 32), dim3(32, 8)>>>(
        W_out, wo, D_INNER, D_MODEL, D_MODEL);

    // 3) zxbcdt = x @ W_in   (launch index 3 -> ncu slot)
    mma_gemm<<<dim3(NPAD1 / 128, ROWS / 128), 256, GSMEM>>>(
        xh, wi, zx_ptr, ROWS, D_IN_PROJ, D_MODEL);

    // 4) dt / dtA
    dt_kernel<<<(BATCH * NHEADS * SEQLEN + 255) / 256, 256>>>(dt_bias, A_log);

    // 5) conv + silu
    conv_kernel<<<((size_t)ROWS * CONV_DIM + 255) / 256, 256>>>(conv_w, conv_b);

    // 6-8) chunked SSM scan
    chunk_state<<<dim3(NCHUNK, NHEADS, BATCH), 256>>>();
    state_pass<<<BATCH * NHEADS, 256>>>();
    chunk_output<<<dim3(NCHUNK, NHEADS, BATCH), 256, CSMEM>>>(Dp);

    // 9) gate + RMSNorm
    norm_kernel<<<ROWS, 256>>>(norm_w);

    // 10) out = y @ W_out
    mma_gemm<<<dim3(D_MODEL / 128, ROWS / 128), 256, GSMEM>>>(
        yh, wo, out, ROWS, D_MODEL, D_INNER);
}